// round 2
// baseline (speedup 1.0000x reference)
#include <cuda_runtime.h>
#include <math.h>

// Problem constants
constexpr int Nn  = 4096;
constexpr int ATT = 64;
constexpr int OUTD = 64;

// ---------------- scratch (device globals; no allocation allowed) ----------------
__device__ float g_Aorig[(size_t)Nn * Nn];     // 67 MB
__device__ float g_A[(size_t)Nn * Nn];         // 67 MB (sigmoid(hh^T) -> An in place)
__device__ float g_H [Nn * 256];               // current h (post-layer)
__device__ float g_H2[Nn * 256];               // An@HW + b
__device__ float g_HW[Nn * 256];               // h@W
__device__ float g_part[(size_t)8 * Nn * 256]; // split-K partials (covers 16x64 and 8x256)
__device__ float g_P0[Nn * ATT];
__device__ float g_P1[Nn * ATT];
__device__ float g_a0[Nn], g_a1[Nn], g_dinv[Nn];
__device__ float g_rs0[Nn], g_rs1[Nn];
__device__ float g_mu[256], g_var[256];

// ---------------- small utility kernels ----------------
__global__ void fill_zero4(float* p, size_t n4) {
    size_t i = (size_t)blockIdx.x * blockDim.x + threadIdx.x;
    if (i < n4) reinterpret_cast<float4*>(p)[i] = make_float4(0.f, 0.f, 0.f, 0.f);
}

__global__ void scatter_edges(const int* __restrict__ ei, const float* __restrict__ ew,
                              float* __restrict__ A, int E) {
    int t = blockIdx.x * blockDim.x + threadIdx.x;
    if (t < E) {
        int r = ei[t];
        int c = ei[E + t];
        atomicAdd(A + (size_t)r * Nn + c, ew[t]);
    }
}

__global__ void rowsum_kernel(const float* __restrict__ A, float* __restrict__ rs) {
    int row = blockIdx.x;
    const float4* p = reinterpret_cast<const float4*>(A + (size_t)row * Nn);
    float s = 0.f;
    for (int i = threadIdx.x; i < Nn / 4; i += blockDim.x) {
        float4 v = p[i];
        s += v.x + v.y + v.z + v.w;
    }
    __shared__ float sh[256];
    sh[threadIdx.x] = s;
    __syncthreads();
    for (int d = 128; d; d >>= 1) {
        if (threadIdx.x < d) sh[threadIdx.x] += sh[threadIdx.x + d];
        __syncthreads();
    }
    if (threadIdx.x == 0) rs[row] = sh[0];
}

// ---------------- GEMM: C = sigmoid(A @ B^T), A,B row-major [4096, K] ----------------
// 128x128 tile, BK=16, 256 threads, 8x8 microtile (2x2 quads of float4)
__global__ __launch_bounds__(256) void gemm_nt_sigmoid(
    const float* __restrict__ A, const float* __restrict__ B,
    float* __restrict__ C, int K)
{
    __shared__ float As[16][132];
    __shared__ float Bs[16][132];
    const int tid = threadIdx.x;
    const int tr = tid >> 4, tc = tid & 15;
    const int bm = blockIdx.y * 128, bn = blockIdx.x * 128;

    float acc[8][8];
#pragma unroll
    for (int i = 0; i < 8; i++)
#pragma unroll
        for (int j = 0; j < 8; j++) acc[i][j] = 0.f;

    for (int k0 = 0; k0 < K; k0 += 16) {
#pragma unroll
        for (int s = 0; s < 2; s++) {
            int slot = tid + s * 256;
            int r = slot >> 2, q = slot & 3;
            float4 va = *reinterpret_cast<const float4*>(A + (size_t)(bm + r) * K + k0 + q * 4);
            As[q * 4 + 0][r] = va.x; As[q * 4 + 1][r] = va.y;
            As[q * 4 + 2][r] = va.z; As[q * 4 + 3][r] = va.w;
            float4 vb = *reinterpret_cast<const float4*>(B + (size_t)(bn + r) * K + k0 + q * 4);
            Bs[q * 4 + 0][r] = vb.x; Bs[q * 4 + 1][r] = vb.y;
            Bs[q * 4 + 2][r] = vb.z; Bs[q * 4 + 3][r] = vb.w;
        }
        __syncthreads();
#pragma unroll
        for (int kk = 0; kk < 16; kk++) {
            float a[8], b[8];
            *reinterpret_cast<float4*>(&a[0]) = *reinterpret_cast<const float4*>(&As[kk][tr * 4]);
            *reinterpret_cast<float4*>(&a[4]) = *reinterpret_cast<const float4*>(&As[kk][64 + tr * 4]);
            *reinterpret_cast<float4*>(&b[0]) = *reinterpret_cast<const float4*>(&Bs[kk][tc * 4]);
            *reinterpret_cast<float4*>(&b[4]) = *reinterpret_cast<const float4*>(&Bs[kk][64 + tc * 4]);
#pragma unroll
            for (int i = 0; i < 8; i++)
#pragma unroll
                for (int j = 0; j < 8; j++) acc[i][j] += a[i] * b[j];
        }
        __syncthreads();
    }

#pragma unroll
    for (int i = 0; i < 8; i++) {
        int row = bm + ((i < 4) ? tr * 4 + i : 64 + tr * 4 + (i - 4));
        float4 v0, v1;
        v0.x = 1.f / (1.f + expf(-acc[i][0]));
        v0.y = 1.f / (1.f + expf(-acc[i][1]));
        v0.z = 1.f / (1.f + expf(-acc[i][2]));
        v0.w = 1.f / (1.f + expf(-acc[i][3]));
        v1.x = 1.f / (1.f + expf(-acc[i][4]));
        v1.y = 1.f / (1.f + expf(-acc[i][5]));
        v1.z = 1.f / (1.f + expf(-acc[i][6]));
        v1.w = 1.f / (1.f + expf(-acc[i][7]));
        *reinterpret_cast<float4*>(C + (size_t)row * Nn + bn + tc * 4) = v0;
        *reinterpret_cast<float4*>(C + (size_t)row * Nn + bn + 64 + tc * 4) = v1;
    }
}

// ---------------- GEMM: part[z] = A[:, zKc:(z+1)Kc] @ B[zKc:(z+1)Kc, :] ----------------
// A row-major [M,K], B row-major [K,Ncols]. 128x64 tile, BK=16, 256 threads, 8x4 microtile.
__global__ __launch_bounds__(256) void gemm_nn_splitk(
    const float* __restrict__ A, const float* __restrict__ B,
    float* __restrict__ part, int M, int Ncols, int K, int Kc)
{
    __shared__ float As[16][132];
    __shared__ float Bs[16][64];
    const int tid = threadIdx.x;
    const int tr = tid >> 4, tc = tid & 15;
    const int bm = blockIdx.y * 128, bn = blockIdx.x * 64;
    const int kbeg = blockIdx.z * Kc;

    float acc[8][4];
#pragma unroll
    for (int i = 0; i < 8; i++)
#pragma unroll
        for (int j = 0; j < 4; j++) acc[i][j] = 0.f;

    for (int k0 = kbeg; k0 < kbeg + Kc; k0 += 16) {
#pragma unroll
        for (int s = 0; s < 2; s++) {
            int slot = tid + s * 256;
            int r = slot >> 2, q = slot & 3;
            float4 va = *reinterpret_cast<const float4*>(A + (size_t)(bm + r) * K + k0 + q * 4);
            As[q * 4 + 0][r] = va.x; As[q * 4 + 1][r] = va.y;
            As[q * 4 + 2][r] = va.z; As[q * 4 + 3][r] = va.w;
        }
        {
            int r = tid >> 4, q = tid & 15;
            *reinterpret_cast<float4*>(&Bs[r][q * 4]) =
                *reinterpret_cast<const float4*>(B + (size_t)(k0 + r) * Ncols + bn + q * 4);
        }
        __syncthreads();
#pragma unroll
        for (int kk = 0; kk < 16; kk++) {
            float a[8], b[4];
            *reinterpret_cast<float4*>(&a[0]) = *reinterpret_cast<const float4*>(&As[kk][tr * 4]);
            *reinterpret_cast<float4*>(&a[4]) = *reinterpret_cast<const float4*>(&As[kk][64 + tr * 4]);
            *reinterpret_cast<float4*>(&b[0]) = *reinterpret_cast<const float4*>(&Bs[kk][tc * 4]);
#pragma unroll
            for (int i = 0; i < 8; i++)
#pragma unroll
                for (int j = 0; j < 4; j++) acc[i][j] += a[i] * b[j];
        }
        __syncthreads();
    }

    float* out = part + (size_t)blockIdx.z * M * Ncols;
#pragma unroll
    for (int i = 0; i < 8; i++) {
        int row = bm + ((i < 4) ? tr * 4 + i : 64 + tr * 4 + (i - 4));
        *reinterpret_cast<float4*>(out + (size_t)row * Ncols + bn + tc * 4) =
            make_float4(acc[i][0], acc[i][1], acc[i][2], acc[i][3]);
    }
}

__global__ void reduce_part(const float* __restrict__ part, float* __restrict__ out,
                            int M, int Ncols, int split, const float* __restrict__ bias) {
    int idx = blockIdx.x * 256 + threadIdx.x;
    int total = M * Ncols;
    if (idx < total) {
        float s = 0.f;
        for (int p = 0; p < split; p++) s += part[(size_t)p * total + idx];
        if (bias) s += bias[idx % Ncols];
        out[idx] = s;
    }
}

// ---------------- attention coefficients + degree/dinv ----------------
// P0/P1 already contain stacked@aw1 + ab1. One warp per node.
__global__ void attention_kernel(const float* __restrict__ P0, const float* __restrict__ P1,
                                 const float* __restrict__ aw2, const float* __restrict__ ab2,
                                 const float* __restrict__ rs0, const float* __restrict__ rs1,
                                 float* __restrict__ a0o, float* __restrict__ a1o,
                                 float* __restrict__ dinv) {
    int warp = (blockIdx.x * blockDim.x + threadIdx.x) >> 5;
    int lane = threadIdx.x & 31;
    if (warp >= Nn) return;
    float s0 = 0.f, s1 = 0.f;
    for (int t = lane; t < ATT; t += 32) {
        float w2 = aw2[t];
        s0 += tanhf(P0[warp * ATT + t]) * w2;
        s1 += tanhf(P1[warp * ATT + t]) * w2;
    }
#pragma unroll
    for (int o = 16; o; o >>= 1) {
        s0 += __shfl_down_sync(0xFFFFFFFFu, s0, o);
        s1 += __shfl_down_sync(0xFFFFFFFFu, s1, o);
    }
    if (lane == 0) {
        float b2 = ab2[0];
        s0 += b2; s1 += b2;
        float m = fmaxf(s0, s1);
        float e0 = expf(s0 - m), e1 = expf(s1 - m);
        float inv = 1.f / (e0 + e1);
        float a0 = e0 * inv, a1 = e1 * inv;
        float deg = a0 * rs0[warp] + a1 * rs1[warp] + 1.f;
        a0o[warp] = a0; a1o[warp] = a1;
        dinv[warp] = deg > 0.f ? rsqrtf(deg) : 0.f;
    }
}

// ---------------- fused A_m + final_A store + An (in place over S) ----------------
__global__ void build_An(const float* __restrict__ Ao, float* __restrict__ S,
                         const float* __restrict__ a0, const float* __restrict__ a1,
                         const float* __restrict__ dinv, float* __restrict__ finalA) {
    size_t gid = (size_t)blockIdx.x * blockDim.x + threadIdx.x;
    if (gid >= (size_t)Nn * Nn / 4) return;
    int i  = (int)(gid / (Nn / 4));
    int j4 = (int)(gid % (Nn / 4)) * 4;
    float4 o = *reinterpret_cast<const float4*>(Ao + (size_t)i * Nn + j4);
    float4 s = *reinterpret_cast<const float4*>(S  + (size_t)i * Nn + j4);
    float A0 = a0[i], A1 = a1[i], di = dinv[i];
    float4 am;
    am.x = A0 * o.x + A1 * s.x;
    am.y = A0 * o.y + A1 * s.y;
    am.z = A0 * o.z + A1 * s.z;
    am.w = A0 * o.w + A1 * s.w;
    if (finalA) *reinterpret_cast<float4*>(finalA + (size_t)i * Nn + j4) = am;
    float4 dj = *reinterpret_cast<const float4*>(dinv + j4);
    float4 an;
    an.x = di * dj.x * (am.x + ((j4 + 0 == i) ? 1.f : 0.f));
    an.y = di * dj.y * (am.y + ((j4 + 1 == i) ? 1.f : 0.f));
    an.z = di * dj.z * (am.z + ((j4 + 2 == i) ? 1.f : 0.f));
    an.w = di * dj.w * (am.w + ((j4 + 3 == i) ? 1.f : 0.f));
    *reinterpret_cast<float4*>(S + (size_t)i * Nn + j4) = an;
}

// ---------------- BatchNorm (two-pass: mean, then centered variance) ----------------
__global__ void bn_stats(const float* __restrict__ H, int dout,
                         float* __restrict__ mu, float* __restrict__ var) {
    int col = blockIdx.x * 32 + threadIdx.x;
    __shared__ float sh[8][32];
    __shared__ float shm[32];

    // pass 1: mean
    float s = 0.f;
    for (int r = threadIdx.y; r < Nn; r += 8)
        s += H[(size_t)r * dout + col];
    sh[threadIdx.y][threadIdx.x] = s;
    __syncthreads();
    if (threadIdx.y == 0) {
#pragma unroll
        for (int y = 1; y < 8; y++) s += sh[y][threadIdx.x];
        shm[threadIdx.x] = s / (float)Nn;
    }
    __syncthreads();
    float m = shm[threadIdx.x];

    // pass 2: centered variance (avoids E[x^2]-E[x]^2 cancellation)
    float s2 = 0.f;
    for (int r = threadIdx.y; r < Nn; r += 8) {
        float d = H[(size_t)r * dout + col] - m;
        s2 += d * d;
    }
    __syncthreads();
    sh[threadIdx.y][threadIdx.x] = s2;
    __syncthreads();
    if (threadIdx.y == 0) {
#pragma unroll
        for (int y = 1; y < 8; y++) s2 += sh[y][threadIdx.x];
        mu[col]  = m;
        var[col] = s2 / (float)Nn;
    }
}

__global__ void bn_apply(const float* __restrict__ Hin, float* __restrict__ Hout, int dout,
                         const float* __restrict__ mu, const float* __restrict__ var,
                         const float* __restrict__ gamma, const float* __restrict__ beta) {
    int idx = blockIdx.x * 256 + threadIdx.x;
    if (idx < Nn * dout) {
        int c = idx % dout;
        float x = Hin[idx];
        float y = gamma[c] * (x - mu[c]) * rsqrtf(var[c] + 1e-5f) + beta[c];
        Hout[idx] = y > 0.f ? y : 0.01f * y;
    }
}

// ---------------- host orchestration ----------------
extern "C" void kernel_launch(void* const* d_in, const int* in_sizes, int n_in,
                              void* d_out, int out_size) {
    const float* X  = (const float*)d_in[0];
    const int*   ei = (const int*)d_in[1];
    const float* ew = (const float*)d_in[2];
    const float *gw[3], *gb[3], *bng[3], *bnb[3], *aw1[3], *ab1[3], *aw2[3], *ab2[3];
    for (int i = 0; i < 3; i++) {
        int b = 3 + i * 8;
        gw[i]  = (const float*)d_in[b + 0];
        gb[i]  = (const float*)d_in[b + 1];
        bng[i] = (const float*)d_in[b + 2];
        bnb[i] = (const float*)d_in[b + 3];
        aw1[i] = (const float*)d_in[b + 4];
        ab1[i] = (const float*)d_in[b + 5];
        aw2[i] = (const float*)d_in[b + 6];
        ab2[i] = (const float*)d_in[b + 7];
    }
    const float* lw = (const float*)d_in[27];
    const float* lb = (const float*)d_in[28];
    const int E = in_sizes[2];

    float *Ao, *Am, *H, *H2, *HW, *part, *P0, *P1, *a0, *a1, *dinv, *rs0, *rs1, *mu, *var;
    cudaGetSymbolAddress((void**)&Ao,   g_Aorig);
    cudaGetSymbolAddress((void**)&Am,   g_A);
    cudaGetSymbolAddress((void**)&H,    g_H);
    cudaGetSymbolAddress((void**)&H2,   g_H2);
    cudaGetSymbolAddress((void**)&HW,   g_HW);
    cudaGetSymbolAddress((void**)&part, g_part);
    cudaGetSymbolAddress((void**)&P0,   g_P0);
    cudaGetSymbolAddress((void**)&P1,   g_P1);
    cudaGetSymbolAddress((void**)&a0,   g_a0);
    cudaGetSymbolAddress((void**)&a1,   g_a1);
    cudaGetSymbolAddress((void**)&dinv, g_dinv);
    cudaGetSymbolAddress((void**)&rs0,  g_rs0);
    cudaGetSymbolAddress((void**)&rs1,  g_rs1);
    cudaGetSymbolAddress((void**)&mu,   g_mu);
    cudaGetSymbolAddress((void**)&var,  g_var);

    // A_orig = scatter(edge_w)
    fill_zero4<<<(int)(((size_t)Nn * Nn / 4 + 255) / 256), 256>>>(Ao, (size_t)Nn * Nn / 4);
    scatter_edges<<<(E + 255) / 256, 256>>>(ei, ew, Ao, E);
    rowsum_kernel<<<Nn, 256>>>(Ao, rs0);

    const float* h = X;
    const int din[3]  = {256, 256, 256};
    const int dof[3]  = {256, 256, 128};

    for (int L = 0; L < 3; L++) {
        const int K = din[L], dout = dof[L];

        // S = sigmoid(h @ h^T)  -> Am
        gemm_nt_sigmoid<<<dim3(32, 32), 256>>>(h, h, Am, K);
        rowsum_kernel<<<Nn, 256>>>(Am, rs1);

        // P0 = A_orig @ aw1 + b1 ; P1 = S @ aw1 + b1   (split-K 16)
        gemm_nn_splitk<<<dim3(1, 32, 16), 256>>>(Ao, aw1[L], part, Nn, ATT, Nn, Nn / 16);
        reduce_part<<<(Nn * ATT + 255) / 256, 256>>>(part, P0, Nn, ATT, 16, ab1[L]);
        gemm_nn_splitk<<<dim3(1, 32, 16), 256>>>(Am, aw1[L], part, Nn, ATT, Nn, Nn / 16);
        reduce_part<<<(Nn * ATT + 255) / 256, 256>>>(part, P1, Nn, ATT, 16, ab1[L]);

        attention_kernel<<<Nn / 4, 128>>>(P0, P1, aw2[L], ab2[L], rs0, rs1, a0, a1, dinv);

        // HW = h @ gw (no bias here; GCN bias applies after aggregation)
        gemm_nn_splitk<<<dim3(dout / 64, 32, 1), 256>>>(h, gw[L], part, Nn, dout, K, K);
        reduce_part<<<(Nn * dout + 255) / 256, 256>>>(part, HW, Nn, dout, 1, nullptr);

        // Build An in place (and stream final_A on last layer)
        float* finalA = nullptr;
        if (L == 2 && out_size >= Nn * OUTD + Nn * Nn)
            finalA = (float*)d_out + (size_t)Nn * OUTD;
        build_An<<<16384, 256>>>(Ao, Am, a0, a1, dinv, finalA);

        // H2 = An @ HW + gb   (split-K 8)
        gemm_nn_splitk<<<dim3(dout / 64, 32, 8), 256>>>(Am, HW, part, Nn, dout, Nn, Nn / 8);
        reduce_part<<<(Nn * dout + 255) / 256, 256>>>(part, H2, Nn, dout, 8, gb[L]);

        // BatchNorm + LeakyReLU -> H
        bn_stats<<<dout / 32, dim3(32, 8)>>>(H2, dout, mu, var);
        bn_apply<<<(Nn * dout + 255) / 256, 256>>>(H2, H, dout, mu, var, bng[L], bnb[L]);
        h = H;
    }

    // out = h @ lin_w + lin_b  (K=128)
    gemm_nn_splitk<<<dim3(1, 32, 1), 256>>>(h, lw, part, Nn, OUTD, 128, 128);
    reduce_part<<<(Nn * OUTD + 255) / 256, 256>>>(part, (float*)d_out, Nn, OUTD, 1, lb);
}

// round 6
// speedup vs baseline: 1.1269x; 1.1269x over previous
#include <cuda_runtime.h>
#include <math.h>
#include <stdint.h>

constexpr int Nn  = 4096;
constexpr int ATT = 64;
constexpr int OUTD = 64;

// ---------------- scratch (device globals; no allocation allowed) ----------------
__device__ float g_Aorig[(size_t)Nn * Nn];
__device__ float g_A[(size_t)Nn * Nn];
__device__ float g_H [Nn * 256];
__device__ float g_H2[Nn * 256];
__device__ float g_HW[Nn * 256];
__device__ float g_HWT[256 * Nn];
__device__ float g_AWT[64 * Nn];
__device__ float g_part[(size_t)4 * Nn * 256];
__device__ float g_P0[Nn * ATT];
__device__ float g_P1[Nn * ATT];
__device__ float g_a0[Nn], g_a1[Nn], g_dinv[Nn];
__device__ float g_rs0[Nn], g_rs1[Nn];
__device__ float g_mu[256], g_var[256];

// ---------------- helpers ----------------
__device__ __forceinline__ uint32_t smem_u32(const void* p) {
    uint32_t a;
    asm("{ .reg .u64 t; cvta.to.shared.u64 t, %1; cvt.u32.u64 %0, t; }" : "=r"(a) : "l"(p));
    return a;
}
__device__ __forceinline__ uint32_t f2tf(float f) {
    uint32_t r;
    asm("cvt.rna.tf32.f32 %0, %1;" : "=r"(r) : "f"(f));
    return r;
}
__device__ __forceinline__ void cpa16(uint32_t dst, const void* src) {
    asm volatile("cp.async.cg.shared.global [%0], [%1], 16;" :: "r"(dst), "l"(src));
}
__device__ __forceinline__ void mma8(float (&c)[4], const uint32_t (&a)[4],
                                     uint32_t b0, uint32_t b1) {
    asm volatile(
        "mma.sync.aligned.m16n8k8.row.col.f32.tf32.tf32.f32 "
        "{%0,%1,%2,%3}, {%4,%5,%6,%7}, {%8,%9}, {%0,%1,%2,%3};"
        : "+f"(c[0]), "+f"(c[1]), "+f"(c[2]), "+f"(c[3])
        : "r"(a[0]), "r"(a[1]), "r"(a[2]), "r"(a[3]), "r"(b0), "r"(b1));
}

// ============================================================================
// tf32x3 NT GEMM via mma.sync: C[M-tile, BN-tile] = A[M,K] * B[N,K]^T
// A, B row-major K-major fp32. 128 x BN CTA tile, BK=32, cp.async double buffer.
// PTX m16n8k8 tf32 fragment layout (g = lane>>2, tg = lane&3):
//   A: a0=(g,tg) a1=(g+8,tg) a2=(g,tg+4) a3=(g+8,tg+4)
//   B: b0=(k=tg,n=g) b1=(k=tg+4,n=g)
//   C: c0,c1=(g, 2tg..2tg+1) c2,c3=(g+8, 2tg..2tg+1)
// EPI: 0 = raw store to part[z]; 1 = sigmoid + atomic rowsum
// ============================================================================
template<int BN, int EPI>
__global__ void __launch_bounds__(256) gemm_mma(
    const float* __restrict__ A, const float* __restrict__ B, float* __restrict__ C,
    int lda, int ldb, int ldc, int nch, long long zstride, float* __restrict__ rs)
{
    constexpr int RS = 36;                       // smem row stride (floats); 36%32=4 -> no conflicts
    constexpr int NT2 = BN / 16;                 // n-tiles (of 8) per warp
    extern __shared__ float smf[];
    float* AsBuf = smf;                          // [2][128*RS]
    float* BsBuf = smf + 2 * 128 * RS;           // [2][BN*RS]

    const int tid  = threadIdx.x;
    const int warp = tid >> 5, lane = tid & 31;
    const int g = lane >> 2, tg = lane & 3;
    const int wm = warp >> 1, wn = warp & 1;
    const int rm = wm * 32, cn = wn * (BN / 2);
    const int bm = blockIdx.y * 128, bn = blockIdx.x * BN;
    const int kbeg = blockIdx.z * nch * 32;

    const uint32_t as_u = smem_u32(AsBuf);
    const uint32_t bs_u = smem_u32(BsBuf);

    auto issue = [&](int c) {
        const int b = c & 1;
        const int k0 = kbeg + c * 32;
        const uint32_t abase = as_u + b * (128 * RS * 4);
        const uint32_t bbase = bs_u + b * (BN * RS * 4);
#pragma unroll
        for (int i = 0; i < 4; i++) {            // A: 128 rows x 32 floats (32 rows/iter)
            int tag = tid + i * 256;
            int r = tag >> 3, q = tag & 7;
            cpa16(abase + (r * RS + q * 4) * 4, A + (size_t)(bm + r) * lda + k0 + q * 4);
        }
#pragma unroll
        for (int i = 0; i < BN / 32; i++) {      // B: BN rows x 32 floats (32 rows/iter)
            int tag = tid + i * 256;
            int r = tag >> 3, q = tag & 7;
            cpa16(bbase + (r * RS + q * 4) * 4, B + (size_t)(bn + r) * ldb + k0 + q * 4);
        }
        asm volatile("cp.async.commit_group;" ::: "memory");
    };

    float acc[2][NT2][4];
#pragma unroll
    for (int mt = 0; mt < 2; mt++)
#pragma unroll
        for (int nt = 0; nt < NT2; nt++)
#pragma unroll
            for (int j = 0; j < 4; j++) acc[mt][nt][j] = 0.f;

    issue(0);
    for (int c = 0; c < nch; c++) {
        if (c + 1 < nch) {
            issue(c + 1);
            asm volatile("cp.async.wait_group 1;" ::: "memory");
        } else {
            asm volatile("cp.async.wait_group 0;" ::: "memory");
        }
        __syncthreads();

        const float* As = AsBuf + (c & 1) * (128 * RS);
        const float* Bs = BsBuf + (c & 1) * (BN * RS);
#pragma unroll
        for (int ks = 0; ks < 4; ks++) {
            const int kb = ks * 8;
            uint32_t ah[2][4], al[2][4];
#pragma unroll
            for (int mt = 0; mt < 2; mt++) {
                const float* r0p = &As[(rm + mt * 16 + g) * RS + kb];
                const float* r1p = &As[(rm + mt * 16 + 8 + g) * RS + kb];
                float x0 = r0p[tg];          // (g,   tg)
                float x1 = r1p[tg];          // (g+8, tg)
                float x2 = r0p[tg + 4];      // (g,   tg+4)
                float x3 = r1p[tg + 4];      // (g+8, tg+4)
                ah[mt][0] = f2tf(x0); al[mt][0] = f2tf(x0 - __uint_as_float(ah[mt][0]));
                ah[mt][1] = f2tf(x1); al[mt][1] = f2tf(x1 - __uint_as_float(ah[mt][1]));
                ah[mt][2] = f2tf(x2); al[mt][2] = f2tf(x2 - __uint_as_float(ah[mt][2]));
                ah[mt][3] = f2tf(x3); al[mt][3] = f2tf(x3 - __uint_as_float(ah[mt][3]));
            }
#pragma unroll
            for (int nt = 0; nt < NT2; nt++) {
                const float* bp = &Bs[(cn + nt * 8 + g) * RS + kb];
                float b0f = bp[tg];          // (k=tg,   n=g)
                float b1f = bp[tg + 4];      // (k=tg+4, n=g)
                uint32_t bh0 = f2tf(b0f), bl0 = f2tf(b0f - __uint_as_float(bh0));
                uint32_t bh1 = f2tf(b1f), bl1 = f2tf(b1f - __uint_as_float(bh1));
#pragma unroll
                for (int mt = 0; mt < 2; mt++) {
                    mma8(acc[mt][nt], ah[mt], bh0, bh1);
                    mma8(acc[mt][nt], ah[mt], bl0, bl1);
                    mma8(acc[mt][nt], al[mt], bh0, bh1);
                }
            }
        }
        __syncthreads();
    }

    // epilogue
    float* Cz = C + (size_t)blockIdx.z * zstride;
#pragma unroll
    for (int mt = 0; mt < 2; mt++) {
        const int r0 = bm + rm + mt * 16 + g;
        const int r1 = r0 + 8;
        float s0 = 0.f, s1 = 0.f;
#pragma unroll
        for (int nt = 0; nt < NT2; nt++) {
            float c0 = acc[mt][nt][0], c1 = acc[mt][nt][1];
            float c2 = acc[mt][nt][2], c3 = acc[mt][nt][3];
            if (EPI == 1) {
                c0 = 1.f / (1.f + expf(-c0)); c1 = 1.f / (1.f + expf(-c1));
                c2 = 1.f / (1.f + expf(-c2)); c3 = 1.f / (1.f + expf(-c3));
                s0 += c0 + c1; s1 += c2 + c3;
            }
            const int col = bn + cn + nt * 8 + 2 * tg;
            *reinterpret_cast<float2*>(Cz + (size_t)r0 * ldc + col) = make_float2(c0, c1);
            *reinterpret_cast<float2*>(Cz + (size_t)r1 * ldc + col) = make_float2(c2, c3);
        }
        if (EPI == 1) {
            s0 += __shfl_xor_sync(0xFFFFFFFFu, s0, 1);
            s0 += __shfl_xor_sync(0xFFFFFFFFu, s0, 2);
            s1 += __shfl_xor_sync(0xFFFFFFFFu, s1, 1);
            s1 += __shfl_xor_sync(0xFFFFFFFFu, s1, 2);
            if (tg == 0) { atomicAdd(rs + r0, s0); atomicAdd(rs + r1, s1); }
        }
    }
}

// ---------------- small utility kernels ----------------
__global__ void fill_zero4(float* p, size_t n4) {
    size_t i = (size_t)blockIdx.x * blockDim.x + threadIdx.x;
    if (i < n4) reinterpret_cast<float4*>(p)[i] = make_float4(0.f, 0.f, 0.f, 0.f);
}

__global__ void scatter_edges(const int* __restrict__ ei, const float* __restrict__ ew,
                              float* __restrict__ A, int E) {
    int t = blockIdx.x * blockDim.x + threadIdx.x;
    if (t < E) {
        int r = ei[t];
        int c = ei[E + t];
        atomicAdd(A + (size_t)r * Nn + c, ew[t]);
    }
}

__global__ void rowsum_kernel(const float* __restrict__ A, float* __restrict__ rs) {
    int row = blockIdx.x;
    const float4* p = reinterpret_cast<const float4*>(A + (size_t)row * Nn);
    float s = 0.f;
    for (int i = threadIdx.x; i < Nn / 4; i += blockDim.x) {
        float4 v = p[i];
        s += v.x + v.y + v.z + v.w;
    }
    __shared__ float sh[256];
    sh[threadIdx.x] = s;
    __syncthreads();
    for (int d = 128; d; d >>= 1) {
        if (threadIdx.x < d) sh[threadIdx.x] += sh[threadIdx.x + d];
        __syncthreads();
    }
    if (threadIdx.x == 0) rs[row] = sh[0];
}

__global__ void transpose_k(const float* __restrict__ in, float* __restrict__ out,
                            int R, int Cc) {
    __shared__ float t[32][33];
    int bx = blockIdx.x * 32, by = blockIdx.y * 32;
    int x = bx + threadIdx.x;
    for (int dy = 0; dy < 32; dy += 8) {
        int y = by + threadIdx.y + dy;
        if (x < Cc && y < R) t[threadIdx.y + dy][threadIdx.x] = in[(size_t)y * Cc + x];
    }
    __syncthreads();
    int xo = by + threadIdx.x;
    for (int dy = 0; dy < 32; dy += 8) {
        int yo = bx + threadIdx.y + dy;
        if (xo < R && yo < Cc) out[(size_t)yo * R + xo] = t[threadIdx.x][threadIdx.y + dy];
    }
}

// ---------------- SIMT GEMM for small-K matmuls (HW = h@gw, final out) -------
__global__ __launch_bounds__(256) void gemm_nn_splitk(
    const float* __restrict__ A, const float* __restrict__ B,
    float* __restrict__ part, int M, int Ncols, int K, int Kc)
{
    __shared__ float As[16][132];
    __shared__ float Bs[16][64];
    const int tid = threadIdx.x;
    const int tr = tid >> 4, tc = tid & 15;
    const int bm = blockIdx.y * 128, bn = blockIdx.x * 64;
    const int kbeg = blockIdx.z * Kc;

    float acc[8][4];
#pragma unroll
    for (int i = 0; i < 8; i++)
#pragma unroll
        for (int j = 0; j < 4; j++) acc[i][j] = 0.f;

    for (int k0 = kbeg; k0 < kbeg + Kc; k0 += 16) {
#pragma unroll
        for (int s = 0; s < 2; s++) {
            int slot = tid + s * 256;
            int r = slot >> 2, q = slot & 3;
            float4 va = *reinterpret_cast<const float4*>(A + (size_t)(bm + r) * K + k0 + q * 4);
            As[q * 4 + 0][r] = va.x; As[q * 4 + 1][r] = va.y;
            As[q * 4 + 2][r] = va.z; As[q * 4 + 3][r] = va.w;
        }
        {
            int r = tid >> 4, q = tid & 15;
            *reinterpret_cast<float4*>(&Bs[r][q * 4]) =
                *reinterpret_cast<const float4*>(B + (size_t)(k0 + r) * Ncols + bn + q * 4);
        }
        __syncthreads();
#pragma unroll
        for (int kk = 0; kk < 16; kk++) {
            float a[8], b[4];
            *reinterpret_cast<float4*>(&a[0]) = *reinterpret_cast<const float4*>(&As[kk][tr * 4]);
            *reinterpret_cast<float4*>(&a[4]) = *reinterpret_cast<const float4*>(&As[kk][64 + tr * 4]);
            *reinterpret_cast<float4*>(&b[0]) = *reinterpret_cast<const float4*>(&Bs[kk][tc * 4]);
#pragma unroll
            for (int i = 0; i < 8; i++)
#pragma unroll
                for (int j = 0; j < 4; j++) acc[i][j] += a[i] * b[j];
        }
        __syncthreads();
    }

    float* out = part + (size_t)blockIdx.z * M * Ncols;
#pragma unroll
    for (int i = 0; i < 8; i++) {
        int row = bm + ((i < 4) ? tr * 4 + i : 64 + tr * 4 + (i - 4));
        *reinterpret_cast<float4*>(out + (size_t)row * Ncols + bn + tc * 4) =
            make_float4(acc[i][0], acc[i][1], acc[i][2], acc[i][3]);
    }
}

__global__ void reduce_part(const float* __restrict__ part, float* __restrict__ out,
                            int M, int Ncols, int split, const float* __restrict__ bias) {
    int idx = blockIdx.x * 256 + threadIdx.x;
    int total = M * Ncols;
    if (idx < total) {
        float s = 0.f;
        for (int p = 0; p < split; p++) s += part[(size_t)p * total + idx];
        if (bias) s += bias[idx % Ncols];
        out[idx] = s;
    }
}

// ---------------- attention coefficients + degree/dinv ----------------
__global__ void attention_kernel(const float* __restrict__ P0, const float* __restrict__ P1,
                                 const float* __restrict__ aw2, const float* __restrict__ ab2,
                                 const float* __restrict__ rs0, const float* __restrict__ rs1,
                                 float* __restrict__ a0o, float* __restrict__ a1o,
                                 float* __restrict__ dinv) {
    int warp = (blockIdx.x * blockDim.x + threadIdx.x) >> 5;
    int lane = threadIdx.x & 31;
    if (warp >= Nn) return;
    float s0 = 0.f, s1 = 0.f;
    for (int t = lane; t < ATT; t += 32) {
        float w2 = aw2[t];
        s0 += tanhf(P0[warp * ATT + t]) * w2;
        s1 += tanhf(P1[warp * ATT + t]) * w2;
    }
#pragma unroll
    for (int o = 16; o; o >>= 1) {
        s0 += __shfl_down_sync(0xFFFFFFFFu, s0, o);
        s1 += __shfl_down_sync(0xFFFFFFFFu, s1, o);
    }
    if (lane == 0) {
        float b2 = ab2[0];
        s0 += b2; s1 += b2;
        float m = fmaxf(s0, s1);
        float e0 = expf(s0 - m), e1 = expf(s1 - m);
        float inv = 1.f / (e0 + e1);
        float a0 = e0 * inv, a1 = e1 * inv;
        float deg = a0 * rs0[warp] + a1 * rs1[warp] + 1.f;
        a0o[warp] = a0; a1o[warp] = a1;
        dinv[warp] = deg > 0.f ? rsqrtf(deg) : 0.f;
    }
}

// ---------------- fused A_m + final_A store + An (in place over S) ----------------
__global__ void build_An(const float* __restrict__ Ao, float* __restrict__ S,
                         const float* __restrict__ a0, const float* __restrict__ a1,
                         const float* __restrict__ dinv, float* __restrict__ finalA) {
    size_t gid = (size_t)blockIdx.x * blockDim.x + threadIdx.x;
    if (gid >= (size_t)Nn * Nn / 4) return;
    int i  = (int)(gid / (Nn / 4));
    int j4 = (int)(gid % (Nn / 4)) * 4;
    float4 o = *reinterpret_cast<const float4*>(Ao + (size_t)i * Nn + j4);
    float4 s = *reinterpret_cast<const float4*>(S  + (size_t)i * Nn + j4);
    float A0 = a0[i], A1 = a1[i], di = dinv[i];
    float4 am;
    am.x = A0 * o.x + A1 * s.x;
    am.y = A0 * o.y + A1 * s.y;
    am.z = A0 * o.z + A1 * s.z;
    am.w = A0 * o.w + A1 * s.w;
    if (finalA) *reinterpret_cast<float4*>(finalA + (size_t)i * Nn + j4) = am;
    float4 dj = *reinterpret_cast<const float4*>(dinv + j4);
    float4 an;
    an.x = di * dj.x * (am.x + ((j4 + 0 == i) ? 1.f : 0.f));
    an.y = di * dj.y * (am.y + ((j4 + 1 == i) ? 1.f : 0.f));
    an.z = di * dj.z * (am.z + ((j4 + 2 == i) ? 1.f : 0.f));
    an.w = di * dj.w * (am.w + ((j4 + 3 == i) ? 1.f : 0.f));
    *reinterpret_cast<float4*>(S + (size_t)i * Nn + j4) = an;
}

// ---------------- BatchNorm (two-pass) ----------------
__global__ void bn_stats(const float* __restrict__ H, int dout,
                         float* __restrict__ mu, float* __restrict__ var) {
    int col = blockIdx.x * 32 + threadIdx.x;
    __shared__ float sh[8][32];
    __shared__ float shm[32];

    float s = 0.f;
    for (int r = threadIdx.y; r < Nn; r += 8)
        s += H[(size_t)r * dout + col];
    sh[threadIdx.y][threadIdx.x] = s;
    __syncthreads();
    if (threadIdx.y == 0) {
#pragma unroll
        for (int y = 1; y < 8; y++) s += sh[y][threadIdx.x];
        shm[threadIdx.x] = s / (float)Nn;
    }
    __syncthreads();
    float m = shm[threadIdx.x];

    float s2 = 0.f;
    for (int r = threadIdx.y; r < Nn; r += 8) {
        float d = H[(size_t)r * dout + col] - m;
        s2 += d * d;
    }
    __syncthreads();
    sh[threadIdx.y][threadIdx.x] = s2;
    __syncthreads();
    if (threadIdx.y == 0) {
#pragma unroll
        for (int y = 1; y < 8; y++) s2 += sh[y][threadIdx.x];
        mu[col]  = m;
        var[col] = s2 / (float)Nn;
    }
}

__global__ void bn_apply(const float* __restrict__ Hin, float* __restrict__ Hout, int dout,
                         const float* __restrict__ mu, const float* __restrict__ var,
                         const float* __restrict__ gamma, const float* __restrict__ beta) {
    int idx = blockIdx.x * 256 + threadIdx.x;
    if (idx < Nn * dout) {
        int c = idx % dout;
        float x = Hin[idx];
        float y = gamma[c] * (x - mu[c]) * rsqrtf(var[c] + 1e-5f) + beta[c];
        Hout[idx] = y > 0.f ? y : 0.01f * y;
    }
}

// ---------------- host orchestration ----------------
extern "C" void kernel_launch(void* const* d_in, const int* in_sizes, int n_in,
                              void* d_out, int out_size) {
    const float* X  = (const float*)d_in[0];
    const int*   ei = (const int*)d_in[1];
    const float* ew = (const float*)d_in[2];
    const float *gw[3], *gb[3], *bng[3], *bnb[3], *aw1[3], *ab1[3], *aw2[3], *ab2[3];
    for (int i = 0; i < 3; i++) {
        int b = 3 + i * 8;
        gw[i]  = (const float*)d_in[b + 0];
        gb[i]  = (const float*)d_in[b + 1];
        bng[i] = (const float*)d_in[b + 2];
        bnb[i] = (const float*)d_in[b + 3];
        aw1[i] = (const float*)d_in[b + 4];
        ab1[i] = (const float*)d_in[b + 5];
        aw2[i] = (const float*)d_in[b + 6];
        ab2[i] = (const float*)d_in[b + 7];
    }
    const float* lw = (const float*)d_in[27];
    const float* lb = (const float*)d_in[28];
    const int E = in_sizes[2];

    float *Ao, *Am, *H, *H2, *HW, *HWT, *AWT, *part, *P0, *P1, *a0, *a1, *dinv, *rs0, *rs1, *mu, *var;
    cudaGetSymbolAddress((void**)&Ao,   g_Aorig);
    cudaGetSymbolAddress((void**)&Am,   g_A);
    cudaGetSymbolAddress((void**)&H,    g_H);
    cudaGetSymbolAddress((void**)&H2,   g_H2);
    cudaGetSymbolAddress((void**)&HW,   g_HW);
    cudaGetSymbolAddress((void**)&HWT,  g_HWT);
    cudaGetSymbolAddress((void**)&AWT,  g_AWT);
    cudaGetSymbolAddress((void**)&part, g_part);
    cudaGetSymbolAddress((void**)&P0,   g_P0);
    cudaGetSymbolAddress((void**)&P1,   g_P1);
    cudaGetSymbolAddress((void**)&a0,   g_a0);
    cudaGetSymbolAddress((void**)&a1,   g_a1);
    cudaGetSymbolAddress((void**)&dinv, g_dinv);
    cudaGetSymbolAddress((void**)&rs0,  g_rs0);
    cudaGetSymbolAddress((void**)&rs1,  g_rs1);
    cudaGetSymbolAddress((void**)&mu,   g_mu);
    cudaGetSymbolAddress((void**)&var,  g_var);

    // dynamic smem: 2 buffers of (128 + BN) rows * 36 floats
    const int SM128 = (2 * 128 * 36 + 2 * 128 * 36) * 4;  // 73728
    const int SM64  = (2 * 128 * 36 + 2 *  64 * 36) * 4;  // 55296
    cudaFuncSetAttribute(gemm_mma<128, 1>, cudaFuncAttributeMaxDynamicSharedMemorySize, SM128);
    cudaFuncSetAttribute(gemm_mma<128, 0>, cudaFuncAttributeMaxDynamicSharedMemorySize, SM128);
    cudaFuncSetAttribute(gemm_mma<64, 0>,  cudaFuncAttributeMaxDynamicSharedMemorySize, SM64);

    // A_orig = scatter(edge_w); rs0 = rowsum(A_orig)
    fill_zero4<<<(int)(((size_t)Nn * Nn / 4 + 255) / 256), 256>>>(Ao, (size_t)Nn * Nn / 4);
    scatter_edges<<<(E + 255) / 256, 256>>>(ei, ew, Ao, E);
    rowsum_kernel<<<Nn, 256>>>(Ao, rs0);

    const float* h = X;
    const int din[3] = {256, 256, 256};
    const int dof[3] = {256, 256, 128};

    for (int L = 0; L < 3; L++) {
        const int K = din[L], dout = dof[L];

        // S = sigmoid(h @ h^T) with fused rowsum -> rs1
        fill_zero4<<<4, 256>>>(rs1, Nn / 4);
        gemm_mma<128, 1><<<dim3(32, 32, 1), 256, SM128>>>(
            h, h, Am, K, K, Nn, K / 32, 0LL, rs1);

        // attention projections: P = [Ao|S] @ aw1 + ab1 (tensor, split-K 4)
        transpose_k<<<dim3(2, Nn / 32), dim3(32, 8)>>>(aw1[L], AWT, Nn, ATT);
        gemm_mma<64, 0><<<dim3(1, 32, 4), 256, SM64>>>(
            Ao, AWT, part, Nn, Nn, ATT, (Nn / 32) / 4, (long long)Nn * ATT, nullptr);
        reduce_part<<<(Nn * ATT + 255) / 256, 256>>>(part, P0, Nn, ATT, 4, ab1[L]);
        gemm_mma<64, 0><<<dim3(1, 32, 4), 256, SM64>>>(
            Am, AWT, part, Nn, Nn, ATT, (Nn / 32) / 4, (long long)Nn * ATT, nullptr);
        reduce_part<<<(Nn * ATT + 255) / 256, 256>>>(part, P1, Nn, ATT, 4, ab1[L]);

        attention_kernel<<<Nn / 4, 128>>>(P0, P1, aw2[L], ab2[L], rs0, rs1, a0, a1, dinv);

        // HW = h @ gw (SIMT, K=256), then HWT = HW^T for the NT tensor GEMM
        gemm_nn_splitk<<<dim3(dout / 64, 32, 1), 256>>>(h, gw[L], part, Nn, dout, K, K);
        reduce_part<<<(Nn * dout + 255) / 256, 256>>>(part, HW, Nn, dout, 1, nullptr);
        transpose_k<<<dim3(dout / 32, Nn / 32), dim3(32, 8)>>>(HW, HWT, Nn, dout);

        // Build An in place (and stream final_A on last layer)
        float* finalA = nullptr;
        if (L == 2 && out_size >= Nn * OUTD + Nn * Nn)
            finalA = (float*)d_out + (size_t)Nn * OUTD;
        build_An<<<16384, 256>>>(Ao, Am, a0, a1, dinv, finalA);

        // H2 = An @ HW + gb (tensor, split-K 2)
        gemm_mma<128, 0><<<dim3(dout / 128, 32, 2), 256, SM128>>>(
            Am, HWT, part, Nn, Nn, dout, (Nn / 32) / 2, (long long)Nn * dout, nullptr);
        reduce_part<<<(Nn * dout + 255) / 256, 256>>>(part, H2, Nn, dout, 2, gb[L]);

        // BatchNorm + LeakyReLU -> H
        bn_stats<<<dout / 32, dim3(32, 8)>>>(H2, dout, mu, var);
        bn_apply<<<(Nn * dout + 255) / 256, 256>>>(H2, H, dout, mu, var, bng[L], bnb[L]);
        h = H;
    }

    // out = h @ lin_w + lin_b (K=128, SIMT)
    gemm_nn_splitk<<<dim3(1, 32, 1), 256>>>(h, lw, part, Nn, OUTD, 128, 128);
    reduce_part<<<(Nn * OUTD + 255) / 256, 256>>>(part, (float*)d_out, Nn, OUTD, 1, lb);
}

// round 7
// speedup vs baseline: 1.2135x; 1.0768x over previous
#include <cuda_runtime.h>
#include <math.h>
#include <stdint.h>

constexpr int Nn  = 4096;
constexpr int ATT = 64;
constexpr int OUTD = 64;

// ---------------- scratch (device globals; no allocation allowed) ----------------
__device__ float g_Aorig[(size_t)Nn * Nn];
__device__ float g_A[(size_t)Nn * Nn];
__device__ float g_H [Nn * 256];
__device__ float g_H2[Nn * 256];
__device__ float g_HW[Nn * 256];
__device__ float g_HWT[256 * Nn];
__device__ float g_AWT[64 * Nn];
__device__ float g_part[(size_t)4 * Nn * 256];
__device__ float g_P0[Nn * ATT];
__device__ float g_P1[Nn * ATT];
__device__ float g_rspart[64 * Nn];            // sigmoid rowsum partials [64][Nn]
__device__ float g_a0[Nn], g_a1[Nn], g_dinv[Nn];
__device__ float g_rs0[Nn];
__device__ float g_mu[256], g_var[256];

// ---------------- helpers ----------------
__device__ __forceinline__ uint32_t smem_u32(const void* p) {
    uint32_t a;
    asm("{ .reg .u64 t; cvta.to.shared.u64 t, %1; cvt.u32.u64 %0, t; }" : "=r"(a) : "l"(p));
    return a;
}
__device__ __forceinline__ uint32_t f2tf(float f) {
    uint32_t r;
    asm("cvt.rna.tf32.f32 %0, %1;" : "=r"(r) : "f"(f));
    return r;
}
__device__ __forceinline__ void cpa16(uint32_t dst, const void* src) {
    asm volatile("cp.async.cg.shared.global [%0], [%1], 16;" :: "r"(dst), "l"(src));
}
__device__ __forceinline__ void mma8(float (&c)[4], const uint32_t (&a)[4],
                                     uint32_t b0, uint32_t b1) {
    asm volatile(
        "mma.sync.aligned.m16n8k8.row.col.f32.tf32.tf32.f32 "
        "{%0,%1,%2,%3}, {%4,%5,%6,%7}, {%8,%9}, {%0,%1,%2,%3};"
        : "+f"(c[0]), "+f"(c[1]), "+f"(c[2]), "+f"(c[3])
        : "r"(a[0]), "r"(a[1]), "r"(a[2]), "r"(a[3]), "r"(b0), "r"(b1));
}

// ============================================================================
// tf32x3 NT GEMM via mma.sync: C[M-tile, BN-tile] = A[M,K] * B[N,K]^T
// EPI: 0 = raw store to part[z]; 1 = sigmoid + rowsum partial store
// ============================================================================
template<int BN, int EPI>
__global__ void __launch_bounds__(256) gemm_mma(
    const float* __restrict__ A, const float* __restrict__ B, float* __restrict__ C,
    int lda, int ldb, int ldc, int nch, long long zstride, float* __restrict__ rs)
{
    constexpr int RS = 36;                       // smem row stride (floats); conflict-free
    constexpr int NT2 = BN / 16;                 // n-tiles (of 8) per warp
    extern __shared__ float smf[];
    float* AsBuf = smf;                          // [2][128*RS]
    float* BsBuf = smf + 2 * 128 * RS;           // [2][BN*RS]

    const int tid  = threadIdx.x;
    const int warp = tid >> 5, lane = tid & 31;
    const int g = lane >> 2, tg = lane & 3;
    const int wm = warp >> 1, wn = warp & 1;
    const int rm = wm * 32, cn = wn * (BN / 2);
    const int bm = blockIdx.y * 128, bn = blockIdx.x * BN;
    const int kbeg = blockIdx.z * nch * 32;

    const uint32_t as_u = smem_u32(AsBuf);
    const uint32_t bs_u = smem_u32(BsBuf);

    auto issue = [&](int c) {
        const int b = c & 1;
        const int k0 = kbeg + c * 32;
        const uint32_t abase = as_u + b * (128 * RS * 4);
        const uint32_t bbase = bs_u + b * (BN * RS * 4);
#pragma unroll
        for (int i = 0; i < 4; i++) {            // A: 128 rows x 32 floats
            int tag = tid + i * 256;
            int r = tag >> 3, q = tag & 7;
            cpa16(abase + (r * RS + q * 4) * 4, A + (size_t)(bm + r) * lda + k0 + q * 4);
        }
#pragma unroll
        for (int i = 0; i < BN / 32; i++) {      // B: BN rows x 32 floats
            int tag = tid + i * 256;
            int r = tag >> 3, q = tag & 7;
            cpa16(bbase + (r * RS + q * 4) * 4, B + (size_t)(bn + r) * ldb + k0 + q * 4);
        }
        asm volatile("cp.async.commit_group;" ::: "memory");
    };

    float acc[2][NT2][4];
#pragma unroll
    for (int mt = 0; mt < 2; mt++)
#pragma unroll
        for (int nt = 0; nt < NT2; nt++)
#pragma unroll
            for (int j = 0; j < 4; j++) acc[mt][nt][j] = 0.f;

    issue(0);
    for (int c = 0; c < nch; c++) {
        if (c + 1 < nch) {
            issue(c + 1);
            asm volatile("cp.async.wait_group 1;" ::: "memory");
        } else {
            asm volatile("cp.async.wait_group 0;" ::: "memory");
        }
        __syncthreads();

        const float* As = AsBuf + (c & 1) * (128 * RS);
        const float* Bs = BsBuf + (c & 1) * (BN * RS);
#pragma unroll
        for (int ks = 0; ks < 4; ks++) {
            const int kb = ks * 8;
            uint32_t ah[2][4], al[2][4];
#pragma unroll
            for (int mt = 0; mt < 2; mt++) {
                const float* r0p = &As[(rm + mt * 16 + g) * RS + kb];
                const float* r1p = &As[(rm + mt * 16 + 8 + g) * RS + kb];
                float x0 = r0p[tg];
                float x1 = r1p[tg];
                float x2 = r0p[tg + 4];
                float x3 = r1p[tg + 4];
                ah[mt][0] = f2tf(x0); al[mt][0] = f2tf(x0 - __uint_as_float(ah[mt][0]));
                ah[mt][1] = f2tf(x1); al[mt][1] = f2tf(x1 - __uint_as_float(ah[mt][1]));
                ah[mt][2] = f2tf(x2); al[mt][2] = f2tf(x2 - __uint_as_float(ah[mt][2]));
                ah[mt][3] = f2tf(x3); al[mt][3] = f2tf(x3 - __uint_as_float(ah[mt][3]));
            }
#pragma unroll
            for (int nt = 0; nt < NT2; nt++) {
                const float* bp = &Bs[(cn + nt * 8 + g) * RS + kb];
                float b0f = bp[tg];
                float b1f = bp[tg + 4];
                uint32_t bh0 = f2tf(b0f), bl0 = f2tf(b0f - __uint_as_float(bh0));
                uint32_t bh1 = f2tf(b1f), bl1 = f2tf(b1f - __uint_as_float(bh1));
#pragma unroll
                for (int mt = 0; mt < 2; mt++) {
                    mma8(acc[mt][nt], ah[mt], bh0, bh1);
                    mma8(acc[mt][nt], ah[mt], bl0, bl1);
                    mma8(acc[mt][nt], al[mt], bh0, bh1);
                }
            }
        }
        __syncthreads();
    }

    // epilogue
    float* Cz = C + (size_t)blockIdx.z * zstride;
#pragma unroll
    for (int mt = 0; mt < 2; mt++) {
        const int r0 = bm + rm + mt * 16 + g;
        const int r1 = r0 + 8;
        float s0 = 0.f, s1 = 0.f;
#pragma unroll
        for (int nt = 0; nt < NT2; nt++) {
            float c0 = acc[mt][nt][0], c1 = acc[mt][nt][1];
            float c2 = acc[mt][nt][2], c3 = acc[mt][nt][3];
            if (EPI == 1) {
                c0 = 1.f / (1.f + expf(-c0)); c1 = 1.f / (1.f + expf(-c1));
                c2 = 1.f / (1.f + expf(-c2)); c3 = 1.f / (1.f + expf(-c3));
                s0 += c0 + c1; s1 += c2 + c3;
            }
            const int col = bn + cn + nt * 8 + 2 * tg;
            *reinterpret_cast<float2*>(Cz + (size_t)r0 * ldc + col) = make_float2(c0, c1);
            *reinterpret_cast<float2*>(Cz + (size_t)r1 * ldc + col) = make_float2(c2, c3);
        }
        if (EPI == 1) {
            // reduce across the 4 tg lanes of each group g
            s0 += __shfl_xor_sync(0xFFFFFFFFu, s0, 1);
            s0 += __shfl_xor_sync(0xFFFFFFFFu, s0, 2);
            s1 += __shfl_xor_sync(0xFFFFFFFFu, s1, 1);
            s1 += __shfl_xor_sync(0xFFFFFFFFu, s1, 2);
            if (tg == 0) {
                // partial slot: (blockIdx.x * 2 + wn) in [0,64)
                float* rp = rs + (size_t)(blockIdx.x * 2 + wn) * Nn;
                rp[r0] = s0;
                rp[r1] = s1;
            }
        }
    }
}

// ---------------- small utility kernels ----------------
__global__ void fill_zero4(float* p, size_t n4) {
    size_t i = (size_t)blockIdx.x * blockDim.x + threadIdx.x;
    if (i < n4) reinterpret_cast<float4*>(p)[i] = make_float4(0.f, 0.f, 0.f, 0.f);
}

__global__ void scatter_edges(const int* __restrict__ ei, const float* __restrict__ ew,
                              float* __restrict__ A, int E) {
    int t = blockIdx.x * blockDim.x + threadIdx.x;
    if (t < E) {
        int r = ei[t];
        int c = ei[E + t];
        atomicAdd(A + (size_t)r * Nn + c, ew[t]);
    }
}

__global__ void rowsum_kernel(const float* __restrict__ A, float* __restrict__ rs) {
    int row = blockIdx.x;
    const float4* p = reinterpret_cast<const float4*>(A + (size_t)row * Nn);
    float s = 0.f;
    for (int i = threadIdx.x; i < Nn / 4; i += blockDim.x) {
        float4 v = p[i];
        s += v.x + v.y + v.z + v.w;
    }
    __shared__ float sh[256];
    sh[threadIdx.x] = s;
    __syncthreads();
    for (int d = 128; d; d >>= 1) {
        if (threadIdx.x < d) sh[threadIdx.x] += sh[threadIdx.x + d];
        __syncthreads();
    }
    if (threadIdx.x == 0) rs[row] = sh[0];
}

__global__ void transpose_k(const float* __restrict__ in, float* __restrict__ out,
                            int R, int Cc) {
    __shared__ float t[32][33];
    int bx = blockIdx.x * 32, by = blockIdx.y * 32;
    int x = bx + threadIdx.x;
    for (int dy = 0; dy < 32; dy += 8) {
        int y = by + threadIdx.y + dy;
        if (x < Cc && y < R) t[threadIdx.y + dy][threadIdx.x] = in[(size_t)y * Cc + x];
    }
    __syncthreads();
    int xo = by + threadIdx.x;
    for (int dy = 0; dy < 32; dy += 8) {
        int yo = bx + threadIdx.y + dy;
        if (xo < R && yo < Cc) out[(size_t)yo * R + xo] = t[threadIdx.x][threadIdx.y + dy];
    }
}

// ---------------- SIMT GEMM for small-K matmuls (HW = h@gw, final out) -------
__global__ __launch_bounds__(256) void gemm_nn_splitk(
    const float* __restrict__ A, const float* __restrict__ B,
    float* __restrict__ part, int M, int Ncols, int K, int Kc)
{
    __shared__ float As[16][132];
    __shared__ float Bs[16][64];
    const int tid = threadIdx.x;
    const int tr = tid >> 4, tc = tid & 15;
    const int bm = blockIdx.y * 128, bn = blockIdx.x * 64;
    const int kbeg = blockIdx.z * Kc;

    float acc[8][4];
#pragma unroll
    for (int i = 0; i < 8; i++)
#pragma unroll
        for (int j = 0; j < 4; j++) acc[i][j] = 0.f;

    for (int k0 = kbeg; k0 < kbeg + Kc; k0 += 16) {
#pragma unroll
        for (int s = 0; s < 2; s++) {
            int slot = tid + s * 256;
            int r = slot >> 2, q = slot & 3;
            float4 va = *reinterpret_cast<const float4*>(A + (size_t)(bm + r) * K + k0 + q * 4);
            As[q * 4 + 0][r] = va.x; As[q * 4 + 1][r] = va.y;
            As[q * 4 + 2][r] = va.z; As[q * 4 + 3][r] = va.w;
        }
        {
            int r = tid >> 4, q = tid & 15;
            *reinterpret_cast<float4*>(&Bs[r][q * 4]) =
                *reinterpret_cast<const float4*>(B + (size_t)(k0 + r) * Ncols + bn + q * 4);
        }
        __syncthreads();
#pragma unroll
        for (int kk = 0; kk < 16; kk++) {
            float a[8], b[4];
            *reinterpret_cast<float4*>(&a[0]) = *reinterpret_cast<const float4*>(&As[kk][tr * 4]);
            *reinterpret_cast<float4*>(&a[4]) = *reinterpret_cast<const float4*>(&As[kk][64 + tr * 4]);
            *reinterpret_cast<float4*>(&b[0]) = *reinterpret_cast<const float4*>(&Bs[kk][tc * 4]);
#pragma unroll
            for (int i = 0; i < 8; i++)
#pragma unroll
                for (int j = 0; j < 4; j++) acc[i][j] += a[i] * b[j];
        }
        __syncthreads();
    }

    float* out = part + (size_t)blockIdx.z * M * Ncols;
#pragma unroll
    for (int i = 0; i < 8; i++) {
        int row = bm + ((i < 4) ? tr * 4 + i : 64 + tr * 4 + (i - 4));
        *reinterpret_cast<float4*>(out + (size_t)row * Ncols + bn + tc * 4) =
            make_float4(acc[i][0], acc[i][1], acc[i][2], acc[i][3]);
    }
}

__global__ void reduce_part(const float* __restrict__ part, float* __restrict__ out,
                            int M, int Ncols, int split, const float* __restrict__ bias) {
    int idx = blockIdx.x * 256 + threadIdx.x;
    int total = M * Ncols;
    if (idx < total) {
        float s = 0.f;
        for (int p = 0; p < split; p++) s += part[(size_t)p * total + idx];
        if (bias) s += bias[idx % Ncols];
        out[idx] = s;
    }
}

// ---------------- attention coefficients + degree/dinv ----------------
// P0/P1 contain stacked@aw1 + ab1. rs1 comes from 64 partial slots per node.
__global__ void attention_kernel(const float* __restrict__ P0, const float* __restrict__ P1,
                                 const float* __restrict__ aw2, const float* __restrict__ ab2,
                                 const float* __restrict__ rs0, const float* __restrict__ rspart,
                                 float* __restrict__ a0o, float* __restrict__ a1o,
                                 float* __restrict__ dinv) {
    int warp = (blockIdx.x * blockDim.x + threadIdx.x) >> 5;
    int lane = threadIdx.x & 31;
    if (warp >= Nn) return;
    float s0 = 0.f, s1 = 0.f;
    for (int t = lane; t < ATT; t += 32) {
        float w2 = aw2[t];
        s0 += tanhf(P0[warp * ATT + t]) * w2;
        s1 += tanhf(P1[warp * ATT + t]) * w2;
    }
    float sr = rspart[(size_t)lane * Nn + warp] + rspart[(size_t)(lane + 32) * Nn + warp];
#pragma unroll
    for (int o = 16; o; o >>= 1) {
        s0 += __shfl_down_sync(0xFFFFFFFFu, s0, o);
        s1 += __shfl_down_sync(0xFFFFFFFFu, s1, o);
        sr += __shfl_down_sync(0xFFFFFFFFu, sr, o);
    }
    if (lane == 0) {
        float b2 = ab2[0];
        s0 += b2; s1 += b2;
        float m = fmaxf(s0, s1);
        float e0 = expf(s0 - m), e1 = expf(s1 - m);
        float inv = 1.f / (e0 + e1);
        float a0 = e0 * inv, a1 = e1 * inv;
        float deg = a0 * rs0[warp] + a1 * sr + 1.f;
        a0o[warp] = a0; a1o[warp] = a1;
        dinv[warp] = deg > 0.f ? rsqrtf(deg) : 0.f;
    }
}

// ---------------- fused A_m + final_A store + An (in place over S) ----------------
__global__ void build_An(const float* __restrict__ Ao, float* __restrict__ S,
                         const float* __restrict__ a0, const float* __restrict__ a1,
                         const float* __restrict__ dinv, float* __restrict__ finalA) {
    size_t gid = (size_t)blockIdx.x * blockDim.x + threadIdx.x;
    if (gid >= (size_t)Nn * Nn / 4) return;
    int i  = (int)(gid / (Nn / 4));
    int j4 = (int)(gid % (Nn / 4)) * 4;
    float4 o = *reinterpret_cast<const float4*>(Ao + (size_t)i * Nn + j4);
    float4 s = *reinterpret_cast<const float4*>(S  + (size_t)i * Nn + j4);
    float A0 = a0[i], A1 = a1[i], di = dinv[i];
    float4 am;
    am.x = A0 * o.x + A1 * s.x;
    am.y = A0 * o.y + A1 * s.y;
    am.z = A0 * o.z + A1 * s.z;
    am.w = A0 * o.w + A1 * s.w;
    if (finalA) *reinterpret_cast<float4*>(finalA + (size_t)i * Nn + j4) = am;
    float4 dj = *reinterpret_cast<const float4*>(dinv + j4);
    float4 an;
    an.x = di * dj.x * (am.x + ((j4 + 0 == i) ? 1.f : 0.f));
    an.y = di * dj.y * (am.y + ((j4 + 1 == i) ? 1.f : 0.f));
    an.z = di * dj.z * (am.z + ((j4 + 2 == i) ? 1.f : 0.f));
    an.w = di * dj.w * (am.w + ((j4 + 3 == i) ? 1.f : 0.f));
    *reinterpret_cast<float4*>(S + (size_t)i * Nn + j4) = an;
}

// ---------------- BatchNorm (two-pass) ----------------
__global__ void bn_stats(const float* __restrict__ H, int dout,
                         float* __restrict__ mu, float* __restrict__ var) {
    int col = blockIdx.x * 32 + threadIdx.x;
    __shared__ float sh[8][32];
    __shared__ float shm[32];

    float s = 0.f;
    for (int r = threadIdx.y; r < Nn; r += 8)
        s += H[(size_t)r * dout + col];
    sh[threadIdx.y][threadIdx.x] = s;
    __syncthreads();
    if (threadIdx.y == 0) {
#pragma unroll
        for (int y = 1; y < 8; y++) s += sh[y][threadIdx.x];
        shm[threadIdx.x] = s / (float)Nn;
    }
    __syncthreads();
    float m = shm[threadIdx.x];

    float s2 = 0.f;
    for (int r = threadIdx.y; r < Nn; r += 8) {
        float d = H[(size_t)r * dout + col] - m;
        s2 += d * d;
    }
    __syncthreads();
    sh[threadIdx.y][threadIdx.x] = s2;
    __syncthreads();
    if (threadIdx.y == 0) {
#pragma unroll
        for (int y = 1; y < 8; y++) s2 += sh[y][threadIdx.x];
        mu[col]  = m;
        var[col] = s2 / (float)Nn;
    }
}

__global__ void bn_apply(const float* __restrict__ Hin, float* __restrict__ Hout, int dout,
                         const float* __restrict__ mu, const float* __restrict__ var,
                         const float* __restrict__ gamma, const float* __restrict__ beta) {
    int idx = blockIdx.x * 256 + threadIdx.x;
    if (idx < Nn * dout) {
        int c = idx % dout;
        float x = Hin[idx];
        float y = gamma[c] * (x - mu[c]) * rsqrtf(var[c] + 1e-5f) + beta[c];
        Hout[idx] = y > 0.f ? y : 0.01f * y;
    }
}

// ---------------- host orchestration ----------------
extern "C" void kernel_launch(void* const* d_in, const int* in_sizes, int n_in,
                              void* d_out, int out_size) {
    const float* X  = (const float*)d_in[0];
    const int*   ei = (const int*)d_in[1];
    const float* ew = (const float*)d_in[2];
    const float *gw[3], *gb[3], *bng[3], *bnb[3], *aw1[3], *ab1[3], *aw2[3], *ab2[3];
    for (int i = 0; i < 3; i++) {
        int b = 3 + i * 8;
        gw[i]  = (const float*)d_in[b + 0];
        gb[i]  = (const float*)d_in[b + 1];
        bng[i] = (const float*)d_in[b + 2];
        bnb[i] = (const float*)d_in[b + 3];
        aw1[i] = (const float*)d_in[b + 4];
        ab1[i] = (const float*)d_in[b + 5];
        aw2[i] = (const float*)d_in[b + 6];
        ab2[i] = (const float*)d_in[b + 7];
    }
    const float* lw = (const float*)d_in[27];
    const float* lb = (const float*)d_in[28];
    const int E = in_sizes[2];

    float *Ao, *Am, *H, *H2, *HW, *HWT, *AWT, *part, *P0, *P1, *rspart,
          *a0, *a1, *dinv, *rs0, *mu, *var;
    cudaGetSymbolAddress((void**)&Ao,     g_Aorig);
    cudaGetSymbolAddress((void**)&Am,     g_A);
    cudaGetSymbolAddress((void**)&H,      g_H);
    cudaGetSymbolAddress((void**)&H2,     g_H2);
    cudaGetSymbolAddress((void**)&HW,     g_HW);
    cudaGetSymbolAddress((void**)&HWT,    g_HWT);
    cudaGetSymbolAddress((void**)&AWT,    g_AWT);
    cudaGetSymbolAddress((void**)&part,   g_part);
    cudaGetSymbolAddress((void**)&P0,     g_P0);
    cudaGetSymbolAddress((void**)&P1,     g_P1);
    cudaGetSymbolAddress((void**)&rspart, g_rspart);
    cudaGetSymbolAddress((void**)&a0,     g_a0);
    cudaGetSymbolAddress((void**)&a1,     g_a1);
    cudaGetSymbolAddress((void**)&dinv,   g_dinv);
    cudaGetSymbolAddress((void**)&rs0,    g_rs0);
    cudaGetSymbolAddress((void**)&mu,     g_mu);
    cudaGetSymbolAddress((void**)&var,    g_var);

    const int SM128 = (2 * 128 * 36 + 2 * 128 * 36) * 4;  // 73728
    const int SM64  = (2 * 128 * 36 + 2 *  64 * 36) * 4;  // 55296
    cudaFuncSetAttribute(gemm_mma<128, 1>, cudaFuncAttributeMaxDynamicSharedMemorySize, SM128);
    cudaFuncSetAttribute(gemm_mma<128, 0>, cudaFuncAttributeMaxDynamicSharedMemorySize, SM128);
    cudaFuncSetAttribute(gemm_mma<64, 0>,  cudaFuncAttributeMaxDynamicSharedMemorySize, SM64);

    // A_orig = scatter(edge_w); rs0 = rowsum(A_orig)
    fill_zero4<<<(int)(((size_t)Nn * Nn / 4 + 255) / 256), 256>>>(Ao, (size_t)Nn * Nn / 4);
    scatter_edges<<<(E + 255) / 256, 256>>>(ei, ew, Ao, E);
    rowsum_kernel<<<Nn, 256>>>(Ao, rs0);

    const float* h = X;
    const int din[3] = {256, 256, 256};
    const int dof[3] = {256, 256, 128};

    for (int L = 0; L < 3; L++) {
        const int K = din[L], dout = dof[L];

        // S = sigmoid(h @ h^T), rowsum partials -> rspart (launch #4 on L=0: profiled)
        gemm_mma<128, 1><<<dim3(32, 32, 1), 256, SM128>>>(
            h, h, Am, K, K, Nn, K / 32, 0LL, rspart);

        // attention projections: P = [Ao|S] @ aw1 + ab1 (tensor, split-K 8 -> 256 CTAs)
        transpose_k<<<dim3(2, Nn / 32), dim3(32, 8)>>>(aw1[L], AWT, Nn, ATT);
        gemm_mma<64, 0><<<dim3(1, 32, 8), 256, SM64>>>(
            Ao, AWT, part, Nn, Nn, ATT, (Nn / 32) / 8, (long long)Nn * ATT, nullptr);
        reduce_part<<<(Nn * ATT + 255) / 256, 256>>>(part, P0, Nn, ATT, 8, ab1[L]);
        gemm_mma<64, 0><<<dim3(1, 32, 8), 256, SM64>>>(
            Am, AWT, part, Nn, Nn, ATT, (Nn / 32) / 8, (long long)Nn * ATT, nullptr);
        reduce_part<<<(Nn * ATT + 255) / 256, 256>>>(part, P1, Nn, ATT, 8, ab1[L]);

        attention_kernel<<<Nn / 4, 128>>>(P0, P1, aw2[L], ab2[L], rs0, rspart, a0, a1, dinv);

        // HW = h @ gw (SIMT, K=256), then HWT = HW^T
        gemm_nn_splitk<<<dim3(dout / 64, 32, 1), 256>>>(h, gw[L], part, Nn, dout, K, K);
        reduce_part<<<(Nn * dout + 255) / 256, 256>>>(part, HW, Nn, dout, 1, nullptr);
        transpose_k<<<dim3(dout / 32, Nn / 32), dim3(32, 8)>>>(HW, HWT, Nn, dout);

        // Build An in place (stream final_A on last layer)
        float* finalA = nullptr;
        if (L == 2 && out_size >= Nn * OUTD + Nn * Nn)
            finalA = (float*)d_out + (size_t)Nn * OUTD;
        build_An<<<16384, 256>>>(Ao, Am, a0, a1, dinv, finalA);

        // H2 = An @ HW + gb: split-K sized for ~256 CTAs
        const int zsp = (dout == 256) ? 4 : 8;   // grid = (dout/128)*32*zsp = 256
        gemm_mma<128, 0><<<dim3(dout / 128, 32, zsp), 256, SM128>>>(
            Am, HWT, part, Nn, Nn, dout, (Nn / 32) / zsp, (long long)Nn * dout, nullptr);
        reduce_part<<<(Nn * dout + 255) / 256, 256>>>(part, H2, Nn, dout, zsp, gb[L]);

        // BatchNorm + LeakyReLU -> H
        bn_stats<<<dout / 32, dim3(32, 8)>>>(H2, dout, mu, var);
        bn_apply<<<(Nn * dout + 255) / 256, 256>>>(H2, H, dout, mu, var, bng[L], bnb[L]);
        h = H;
    }

    // out = h @ lin_w + lin_b (K=128, SIMT)
    gemm_nn_splitk<<<dim3(1, 32, 1), 256>>>(h, lw, part, Nn, OUTD, 128, 128);
    reduce_part<<<(Nn * OUTD + 255) / 256, 256>>>(part, (float*)d_out, Nn, OUTD, 1, lb);
}

// round 8
// speedup vs baseline: 1.6737x; 1.3793x over previous
#include <cuda_runtime.h>
#include <cuda_fp16.h>
#include <math.h>
#include <stdint.h>

constexpr int Nn  = 4096;
constexpr int ATT = 64;
constexpr int OUTD = 64;
constexpr float SCALE_AN = 16384.f;
constexpr float SCALE_AW = 64.f;

// ---------------- scratch (device globals; no allocation allowed) ----------------
__device__ float g_Aorig[(size_t)Nn * Nn];
__device__ float g_A[(size_t)Nn * Nn];
__device__ float g_H [Nn * 256];
__device__ float g_H2[Nn * 256];
__device__ float g_HW[Nn * 256];
__device__ float g_HWT[256 * Nn];
__device__ float g_AWT[64 * Nn];
__device__ float g_part[(size_t)8 * Nn * 256];
__device__ float g_P0[Nn * ATT];
__device__ float g_P1[Nn * ATT];
__device__ float g_rspart[64 * Nn];            // sigmoid rowsum partials [64][Nn]
__device__ float g_a0[Nn], g_a1[Nn], g_dinv[Nn];
__device__ float g_rs0[Nn];
__device__ float g_mu[256], g_var[256];

// ---------------- helpers ----------------
__device__ __forceinline__ uint32_t smem_u32(const void* p) {
    uint32_t a;
    asm("{ .reg .u64 t; cvta.to.shared.u64 t, %1; cvt.u32.u64 %0, t; }" : "=r"(a) : "l"(p));
    return a;
}
__device__ __forceinline__ void cpa16(uint32_t dst, const void* src) {
    asm volatile("cp.async.cg.shared.global [%0], [%1], 16;" :: "r"(dst), "l"(src));
}
__device__ __forceinline__ void mma16(float (&c)[4], const uint32_t (&a)[4],
                                      uint32_t b0, uint32_t b1) {
    asm volatile(
        "mma.sync.aligned.m16n8k16.row.col.f32.f16.f16.f32 "
        "{%0,%1,%2,%3}, {%4,%5,%6,%7}, {%8,%9}, {%0,%1,%2,%3};"
        : "+f"(c[0]), "+f"(c[1]), "+f"(c[2]), "+f"(c[3])
        : "r"(a[0]), "r"(a[1]), "r"(a[2]), "r"(a[3]), "r"(b0), "r"(b1));
}
// split (x,y) into packed f16 hi pair and lo pair
__device__ __forceinline__ void splitpair(float x, float y, uint32_t& h, uint32_t& l) {
    __half hx = __float2half_rn(x), hy = __float2half_rn(y);
    __half lx = __float2half_rn(x - __half2float(hx));
    __half ly = __float2half_rn(y - __half2float(hy));
    __half2 hp = __halves2half2(hx, hy), lp = __halves2half2(lx, ly);
    h = *reinterpret_cast<uint32_t*>(&hp);
    l = *reinterpret_cast<uint32_t*>(&lp);
}

// ============================================================================
// f16x3 NT GEMM via mma.sync m16n8k16: C = A[M,K] * B[N,K]^T (fp32 in/out)
// hi/lo split done ONCE per CTA in smem (convert stage); MMA loads plain LDS.
// m16n8k16 fragments (g=lane>>2, tg=lane&3), pairs = 2 packed f16:
//   A: a0=(g,pair tg) a1=(g+8,tg) a2=(g,tg+4) a3=(g+8,tg+4)   [pair idx in 16-k blk]
//   B: b0=(pair tg, col g) b1=(pair tg+4, col g)
//   C: c0,c1=(g, 2tg..2tg+1) c2,c3=(g+8, ...)
// EPI: 0 = raw store to part[z]; 1 = sigmoid + rowsum partial store
// ============================================================================
template<int BN, int EPI>
__global__ void __launch_bounds__(256, 2) gemm_f16(
    const float* __restrict__ A, const float* __restrict__ B, float* __restrict__ C,
    int lda, int ldb, int ldc, int nch, long long zstride, float* __restrict__ rs)
{
    constexpr int RAWS = 36;                 // raw staging row stride (floats)
    constexpr int TS   = 20;                 // f16-pair tile row stride (u32); conflict-free
    constexpr int NT2  = BN / 16;
    extern __shared__ char smc[];
    float*    raw = reinterpret_cast<float*>(smc);                       // (128+BN) x RAWS
    uint32_t* Ahi = reinterpret_cast<uint32_t*>(smc + (128 + BN) * RAWS * 4);
    uint32_t* Alo = Ahi + 128 * TS;
    uint32_t* Bhi = Alo + 128 * TS;
    uint32_t* Blo = Bhi + BN * TS;

    const int tid  = threadIdx.x;
    const int warp = tid >> 5, lane = tid & 31;
    const int g = lane >> 2, tg = lane & 3;
    const int wm = warp >> 1, wn = warp & 1;
    const int rm = wm * 32, cn = wn * (BN / 2);
    const int bm = blockIdx.y * 128, bn = blockIdx.x * BN;
    const int kbeg = blockIdx.z * nch * 32;

    const uint32_t raw_u = smem_u32(raw);

    auto issue = [&](int c) {
        const int k0 = kbeg + c * 32;
#pragma unroll
        for (int i = 0; i < 4; i++) {                   // A: 128 rows x 32 floats
            int idx = tid + i * 256;
            int r = idx >> 3, q = idx & 7;
            cpa16(raw_u + (r * RAWS + q * 4) * 4, A + (size_t)(bm + r) * lda + k0 + q * 4);
        }
#pragma unroll
        for (int i = 0; i < BN / 32; i++) {             // B: BN rows x 32 floats
            int idx = tid + i * 256;
            int r = idx >> 3, q = idx & 7;
            cpa16(raw_u + ((128 + r) * RAWS + q * 4) * 4, B + (size_t)(bn + r) * ldb + k0 + q * 4);
        }
        asm volatile("cp.async.commit_group;" ::: "memory");
    };

    float acc[2][NT2][4];
#pragma unroll
    for (int mt = 0; mt < 2; mt++)
#pragma unroll
        for (int nt = 0; nt < NT2; nt++)
#pragma unroll
            for (int j = 0; j < 4; j++) acc[mt][nt][j] = 0.f;

    issue(0);
    for (int c = 0; c < nch; c++) {
        asm volatile("cp.async.wait_group 0;" ::: "memory");
        __syncthreads();                                 // raw ready; tiles free

        // convert raw fp32 -> hi/lo f16-pair tiles (once per CTA)
#pragma unroll
        for (int i = 0; i < 4; i++) {                    // A
            int idx = tid + i * 256;
            int r = idx >> 3, q = idx & 7;
            float4 v = *reinterpret_cast<const float4*>(&raw[r * RAWS + q * 4]);
            uint32_t h0, l0, h1, l1;
            splitpair(v.x, v.y, h0, l0);
            splitpair(v.z, v.w, h1, l1);
            *reinterpret_cast<uint2*>(&Ahi[r * TS + 2 * q]) = make_uint2(h0, h1);
            *reinterpret_cast<uint2*>(&Alo[r * TS + 2 * q]) = make_uint2(l0, l1);
        }
#pragma unroll
        for (int i = 0; i < BN / 32; i++) {              // B
            int idx = tid + i * 256;
            int r = idx >> 3, q = idx & 7;
            float4 v = *reinterpret_cast<const float4*>(&raw[(128 + r) * RAWS + q * 4]);
            uint32_t h0, l0, h1, l1;
            splitpair(v.x, v.y, h0, l0);
            splitpair(v.z, v.w, h1, l1);
            *reinterpret_cast<uint2*>(&Bhi[r * TS + 2 * q]) = make_uint2(h0, h1);
            *reinterpret_cast<uint2*>(&Blo[r * TS + 2 * q]) = make_uint2(l0, l1);
        }
        __syncthreads();                                 // tiles ready; raw free

        if (c + 1 < nch) issue(c + 1);                   // overlap next load with MMA

#pragma unroll
        for (int ks = 0; ks < 2; ks++) {                 // two k16 steps per 32-k chunk
            const int kp = ks * 8;
            uint32_t ah[2][4], al[2][4];
#pragma unroll
            for (int mt = 0; mt < 2; mt++) {
                const int ro = (rm + mt * 16 + g) * TS;
                ah[mt][0] = Ahi[ro + kp + tg];
                ah[mt][1] = Ahi[ro + 8 * TS + kp + tg];
                ah[mt][2] = Ahi[ro + kp + tg + 4];
                ah[mt][3] = Ahi[ro + 8 * TS + kp + tg + 4];
                al[mt][0] = Alo[ro + kp + tg];
                al[mt][1] = Alo[ro + 8 * TS + kp + tg];
                al[mt][2] = Alo[ro + kp + tg + 4];
                al[mt][3] = Alo[ro + 8 * TS + kp + tg + 4];
            }
#pragma unroll
            for (int nt = 0; nt < NT2; nt++) {
                const int bo = (cn + nt * 8 + g) * TS + kp;
                uint32_t b0h = Bhi[bo + tg], b1h = Bhi[bo + tg + 4];
                uint32_t b0l = Blo[bo + tg], b1l = Blo[bo + tg + 4];
#pragma unroll
                for (int mt = 0; mt < 2; mt++) {
                    mma16(acc[mt][nt], ah[mt], b0h, b1h);
                    mma16(acc[mt][nt], ah[mt], b0l, b1l);
                    mma16(acc[mt][nt], al[mt], b0h, b1h);
                }
            }
        }
    }

    // epilogue
    float* Cz = C + (size_t)blockIdx.z * zstride;
#pragma unroll
    for (int mt = 0; mt < 2; mt++) {
        const int r0 = bm + rm + mt * 16 + g;
        const int r1 = r0 + 8;
        float s0 = 0.f, s1 = 0.f;
#pragma unroll
        for (int nt = 0; nt < NT2; nt++) {
            float c0 = acc[mt][nt][0], c1 = acc[mt][nt][1];
            float c2 = acc[mt][nt][2], c3 = acc[mt][nt][3];
            if (EPI == 1) {
                c0 = 1.f / (1.f + expf(-c0)); c1 = 1.f / (1.f + expf(-c1));
                c2 = 1.f / (1.f + expf(-c2)); c3 = 1.f / (1.f + expf(-c3));
                s0 += c0 + c1; s1 += c2 + c3;
            }
            const int col = bn + cn + nt * 8 + 2 * tg;
            *reinterpret_cast<float2*>(Cz + (size_t)r0 * ldc + col) = make_float2(c0, c1);
            *reinterpret_cast<float2*>(Cz + (size_t)r1 * ldc + col) = make_float2(c2, c3);
        }
        if (EPI == 1) {
            s0 += __shfl_xor_sync(0xFFFFFFFFu, s0, 1);
            s0 += __shfl_xor_sync(0xFFFFFFFFu, s0, 2);
            s1 += __shfl_xor_sync(0xFFFFFFFFu, s1, 1);
            s1 += __shfl_xor_sync(0xFFFFFFFFu, s1, 2);
            if (tg == 0) {
                float* rp = rs + (size_t)(blockIdx.x * 2 + wn) * Nn;
                rp[r0] = s0;
                rp[r1] = s1;
            }
        }
    }
}

// ---------------- small utility kernels ----------------
__global__ void fill_zero4(float* p, size_t n4) {
    size_t i = (size_t)blockIdx.x * blockDim.x + threadIdx.x;
    if (i < n4) reinterpret_cast<float4*>(p)[i] = make_float4(0.f, 0.f, 0.f, 0.f);
}

__global__ void scatter_edges(const int* __restrict__ ei, const float* __restrict__ ew,
                              float* __restrict__ A, int E) {
    int t = blockIdx.x * blockDim.x + threadIdx.x;
    if (t < E) {
        int r = ei[t];
        int c = ei[E + t];
        atomicAdd(A + (size_t)r * Nn + c, ew[t]);
    }
}

__global__ void rowsum_kernel(const float* __restrict__ A, float* __restrict__ rs) {
    int row = blockIdx.x;
    const float4* p = reinterpret_cast<const float4*>(A + (size_t)row * Nn);
    float s = 0.f;
    for (int i = threadIdx.x; i < Nn / 4; i += blockDim.x) {
        float4 v = p[i];
        s += v.x + v.y + v.z + v.w;
    }
    __shared__ float sh[256];
    sh[threadIdx.x] = s;
    __syncthreads();
    for (int d = 128; d; d >>= 1) {
        if (threadIdx.x < d) sh[threadIdx.x] += sh[threadIdx.x + d];
        __syncthreads();
    }
    if (threadIdx.x == 0) rs[row] = sh[0];
}

__global__ void transpose_k(const float* __restrict__ in, float* __restrict__ out,
                            int R, int Cc, float scale) {
    __shared__ float t[32][33];
    int bx = blockIdx.x * 32, by = blockIdx.y * 32;
    int x = bx + threadIdx.x;
    for (int dy = 0; dy < 32; dy += 8) {
        int y = by + threadIdx.y + dy;
        if (x < Cc && y < R) t[threadIdx.y + dy][threadIdx.x] = in[(size_t)y * Cc + x];
    }
    __syncthreads();
    int xo = by + threadIdx.x;
    for (int dy = 0; dy < 32; dy += 8) {
        int yo = bx + threadIdx.y + dy;
        if (xo < R && yo < Cc) out[(size_t)yo * R + xo] = t[threadIdx.x][threadIdx.y + dy] * scale;
    }
}

// ---------------- SIMT GEMM for small-K matmuls (HW = h@gw, final out) -------
__global__ __launch_bounds__(256) void gemm_nn_splitk(
    const float* __restrict__ A, const float* __restrict__ B,
    float* __restrict__ part, int M, int Ncols, int K, int Kc)
{
    __shared__ float As[16][132];
    __shared__ float Bs[16][64];
    const int tid = threadIdx.x;
    const int tr = tid >> 4, tc = tid & 15;
    const int bm = blockIdx.y * 128, bn = blockIdx.x * 64;
    const int kbeg = blockIdx.z * Kc;

    float acc[8][4];
#pragma unroll
    for (int i = 0; i < 8; i++)
#pragma unroll
        for (int j = 0; j < 4; j++) acc[i][j] = 0.f;

    for (int k0 = kbeg; k0 < kbeg + Kc; k0 += 16) {
#pragma unroll
        for (int s = 0; s < 2; s++) {
            int slot = tid + s * 256;
            int r = slot >> 2, q = slot & 3;
            float4 va = *reinterpret_cast<const float4*>(A + (size_t)(bm + r) * K + k0 + q * 4);
            As[q * 4 + 0][r] = va.x; As[q * 4 + 1][r] = va.y;
            As[q * 4 + 2][r] = va.z; As[q * 4 + 3][r] = va.w;
        }
        {
            int r = tid >> 4, q = tid & 15;
            *reinterpret_cast<float4*>(&Bs[r][q * 4]) =
                *reinterpret_cast<const float4*>(B + (size_t)(k0 + r) * Ncols + bn + q * 4);
        }
        __syncthreads();
#pragma unroll
        for (int kk = 0; kk < 16; kk++) {
            float a[8], b[4];
            *reinterpret_cast<float4*>(&a[0]) = *reinterpret_cast<const float4*>(&As[kk][tr * 4]);
            *reinterpret_cast<float4*>(&a[4]) = *reinterpret_cast<const float4*>(&As[kk][64 + tr * 4]);
            *reinterpret_cast<float4*>(&b[0]) = *reinterpret_cast<const float4*>(&Bs[kk][tc * 4]);
#pragma unroll
            for (int i = 0; i < 8; i++)
#pragma unroll
                for (int j = 0; j < 4; j++) acc[i][j] += a[i] * b[j];
        }
        __syncthreads();
    }

    float* out = part + (size_t)blockIdx.z * M * Ncols;
#pragma unroll
    for (int i = 0; i < 8; i++) {
        int row = bm + ((i < 4) ? tr * 4 + i : 64 + tr * 4 + (i - 4));
        *reinterpret_cast<float4*>(out + (size_t)row * Ncols + bn + tc * 4) =
            make_float4(acc[i][0], acc[i][1], acc[i][2], acc[i][3]);
    }
}

__global__ void reduce_part(const float* __restrict__ part, float* __restrict__ out,
                            int M, int Ncols, int split, const float* __restrict__ bias,
                            float scale) {
    int idx = blockIdx.x * 256 + threadIdx.x;
    int total = M * Ncols;
    if (idx < total) {
        float s = 0.f;
        for (int p = 0; p < split; p++) s += part[(size_t)p * total + idx];
        s *= scale;
        if (bias) s += bias[idx % Ncols];
        out[idx] = s;
    }
}

// ---------------- attention coefficients + degree/dinv ----------------
__global__ void attention_kernel(const float* __restrict__ P0, const float* __restrict__ P1,
                                 const float* __restrict__ aw2, const float* __restrict__ ab2,
                                 const float* __restrict__ rs0, const float* __restrict__ rspart,
                                 float* __restrict__ a0o, float* __restrict__ a1o,
                                 float* __restrict__ dinv) {
    int warp = (blockIdx.x * blockDim.x + threadIdx.x) >> 5;
    int lane = threadIdx.x & 31;
    if (warp >= Nn) return;
    float s0 = 0.f, s1 = 0.f;
    for (int t = lane; t < ATT; t += 32) {
        float w2 = aw2[t];
        s0 += tanhf(P0[warp * ATT + t]) * w2;
        s1 += tanhf(P1[warp * ATT + t]) * w2;
    }
    float sr = rspart[(size_t)lane * Nn + warp] + rspart[(size_t)(lane + 32) * Nn + warp];
#pragma unroll
    for (int o = 16; o; o >>= 1) {
        s0 += __shfl_down_sync(0xFFFFFFFFu, s0, o);
        s1 += __shfl_down_sync(0xFFFFFFFFu, s1, o);
        sr += __shfl_down_sync(0xFFFFFFFFu, sr, o);
    }
    if (lane == 0) {
        float b2 = ab2[0];
        s0 += b2; s1 += b2;
        float m = fmaxf(s0, s1);
        float e0 = expf(s0 - m), e1 = expf(s1 - m);
        float inv = 1.f / (e0 + e1);
        float a0 = e0 * inv, a1 = e1 * inv;
        float deg = a0 * rs0[warp] + a1 * sr + 1.f;
        a0o[warp] = a0; a1o[warp] = a1;
        dinv[warp] = deg > 0.f ? rsqrtf(deg) : 0.f;
    }
}

// ---------------- fused A_m + final_A store + An (scaled, in place over S) --------
__global__ void build_An(const float* __restrict__ Ao, float* __restrict__ S,
                         const float* __restrict__ a0, const float* __restrict__ a1,
                         const float* __restrict__ dinv, float* __restrict__ finalA) {
    size_t gid = (size_t)blockIdx.x * blockDim.x + threadIdx.x;
    if (gid >= (size_t)Nn * Nn / 4) return;
    int i  = (int)(gid / (Nn / 4));
    int j4 = (int)(gid % (Nn / 4)) * 4;
    float4 o = *reinterpret_cast<const float4*>(Ao + (size_t)i * Nn + j4);
    float4 s = *reinterpret_cast<const float4*>(S  + (size_t)i * Nn + j4);
    float A0 = a0[i], A1 = a1[i], di = dinv[i] * SCALE_AN;
    float4 am;
    am.x = A0 * o.x + A1 * s.x;
    am.y = A0 * o.y + A1 * s.y;
    am.z = A0 * o.z + A1 * s.z;
    am.w = A0 * o.w + A1 * s.w;
    if (finalA) *reinterpret_cast<float4*>(finalA + (size_t)i * Nn + j4) = am;
    float4 dj = *reinterpret_cast<const float4*>(dinv + j4);
    float4 an;
    an.x = di * dj.x * (am.x + ((j4 + 0 == i) ? 1.f : 0.f));
    an.y = di * dj.y * (am.y + ((j4 + 1 == i) ? 1.f : 0.f));
    an.z = di * dj.z * (am.z + ((j4 + 2 == i) ? 1.f : 0.f));
    an.w = di * dj.w * (am.w + ((j4 + 3 == i) ? 1.f : 0.f));
    *reinterpret_cast<float4*>(S + (size_t)i * Nn + j4) = an;
}

// ---------------- BatchNorm (two-pass) ----------------
__global__ void bn_stats(const float* __restrict__ H, int dout,
                         float* __restrict__ mu, float* __restrict__ var) {
    int col = blockIdx.x * 32 + threadIdx.x;
    __shared__ float sh[8][32];
    __shared__ float shm[32];

    float s = 0.f;
    for (int r = threadIdx.y; r < Nn; r += 8)
        s += H[(size_t)r * dout + col];
    sh[threadIdx.y][threadIdx.x] = s;
    __syncthreads();
    if (threadIdx.y == 0) {
#pragma unroll
        for (int y = 1; y < 8; y++) s += sh[y][threadIdx.x];
        shm[threadIdx.x] = s / (float)Nn;
    }
    __syncthreads();
    float m = shm[threadIdx.x];

    float s2 = 0.f;
    for (int r = threadIdx.y; r < Nn; r += 8) {
        float d = H[(size_t)r * dout + col] - m;
        s2 += d * d;
    }
    __syncthreads();
    sh[threadIdx.y][threadIdx.x] = s2;
    __syncthreads();
    if (threadIdx.y == 0) {
#pragma unroll
        for (int y = 1; y < 8; y++) s2 += sh[y][threadIdx.x];
        mu[col]  = m;
        var[col] = s2 / (float)Nn;
    }
}

__global__ void bn_apply(const float* __restrict__ Hin, float* __restrict__ Hout, int dout,
                         const float* __restrict__ mu, const float* __restrict__ var,
                         const float* __restrict__ gamma, const float* __restrict__ beta) {
    int idx = blockIdx.x * 256 + threadIdx.x;
    if (idx < Nn * dout) {
        int c = idx % dout;
        float x = Hin[idx];
        float y = gamma[c] * (x - mu[c]) * rsqrtf(var[c] + 1e-5f) + beta[c];
        Hout[idx] = y > 0.f ? y : 0.01f * y;
    }
}

// ---------------- host orchestration ----------------
extern "C" void kernel_launch(void* const* d_in, const int* in_sizes, int n_in,
                              void* d_out, int out_size) {
    const float* X  = (const float*)d_in[0];
    const int*   ei = (const int*)d_in[1];
    const float* ew = (const float*)d_in[2];
    const float *gw[3], *gb[3], *bng[3], *bnb[3], *aw1[3], *ab1[3], *aw2[3], *ab2[3];
    for (int i = 0; i < 3; i++) {
        int b = 3 + i * 8;
        gw[i]  = (const float*)d_in[b + 0];
        gb[i]  = (const float*)d_in[b + 1];
        bng[i] = (const float*)d_in[b + 2];
        bnb[i] = (const float*)d_in[b + 3];
        aw1[i] = (const float*)d_in[b + 4];
        ab1[i] = (const float*)d_in[b + 5];
        aw2[i] = (const float*)d_in[b + 6];
        ab2[i] = (const float*)d_in[b + 7];
    }
    const float* lw = (const float*)d_in[27];
    const float* lb = (const float*)d_in[28];
    const int E = in_sizes[2];

    float *Ao, *Am, *H, *H2, *HW, *HWT, *AWT, *part, *P0, *P1, *rspart,
          *a0, *a1, *dinv, *rs0, *mu, *var;
    cudaGetSymbolAddress((void**)&Ao,     g_Aorig);
    cudaGetSymbolAddress((void**)&Am,     g_A);
    cudaGetSymbolAddress((void**)&H,      g_H);
    cudaGetSymbolAddress((void**)&H2,     g_H2);
    cudaGetSymbolAddress((void**)&HW,     g_HW);
    cudaGetSymbolAddress((void**)&HWT,    g_HWT);
    cudaGetSymbolAddress((void**)&AWT,    g_AWT);
    cudaGetSymbolAddress((void**)&part,   g_part);
    cudaGetSymbolAddress((void**)&P0,     g_P0);
    cudaGetSymbolAddress((void**)&P1,     g_P1);
    cudaGetSymbolAddress((void**)&rspart, g_rspart);
    cudaGetSymbolAddress((void**)&a0,     g_a0);
    cudaGetSymbolAddress((void**)&a1,     g_a1);
    cudaGetSymbolAddress((void**)&dinv,   g_dinv);
    cudaGetSymbolAddress((void**)&rs0,    g_rs0);
    cudaGetSymbolAddress((void**)&mu,     g_mu);
    cudaGetSymbolAddress((void**)&var,    g_var);

    // smem: raw (128+BN)x36 f32 + 4 tiles (128/BN rows x 20 u32)
    const int SM128 = (256 * 36 * 4) + (512 * 20 * 4);   // 36864 + 40960 = 77824
    const int SM64  = (192 * 36 * 4) + (384 * 20 * 4);   // 27648 + 30720 = 58368
    cudaFuncSetAttribute(gemm_f16<128, 1>, cudaFuncAttributeMaxDynamicSharedMemorySize, SM128);
    cudaFuncSetAttribute(gemm_f16<128, 0>, cudaFuncAttributeMaxDynamicSharedMemorySize, SM128);
    cudaFuncSetAttribute(gemm_f16<64, 0>,  cudaFuncAttributeMaxDynamicSharedMemorySize, SM64);

    // A_orig = scatter(edge_w); rs0 = rowsum(A_orig)
    fill_zero4<<<(int)(((size_t)Nn * Nn / 4 + 255) / 256), 256>>>(Ao, (size_t)Nn * Nn / 4);
    scatter_edges<<<(E + 255) / 256, 256>>>(ei, ew, Ao, E);
    rowsum_kernel<<<Nn, 256>>>(Ao, rs0);

    const float* h = X;
    const int din[3] = {256, 256, 256};
    const int dof[3] = {256, 256, 128};

    for (int L = 0; L < 3; L++) {
        const int K = din[L], dout = dof[L];

        // S = sigmoid(h @ h^T), rowsum partials -> rspart (launch #4 on L=0: profiled)
        gemm_f16<128, 1><<<dim3(32, 32, 1), 256, SM128>>>(
            h, h, Am, K, K, Nn, K / 32, 0LL, rspart);

        // attention projections: P = [Ao|S] @ (64*aw1) / 64 + ab1  (split-K 8)
        transpose_k<<<dim3(2, Nn / 32), dim3(32, 8)>>>(aw1[L], AWT, Nn, ATT, SCALE_AW);
        gemm_f16<64, 0><<<dim3(1, 32, 8), 256, SM64>>>(
            Ao, AWT, part, Nn, Nn, ATT, (Nn / 32) / 8, (long long)Nn * ATT, nullptr);
        reduce_part<<<(Nn * ATT + 255) / 256, 256>>>(part, P0, Nn, ATT, 8, ab1[L], 1.f / SCALE_AW);
        gemm_f16<64, 0><<<dim3(1, 32, 8), 256, SM64>>>(
            Am, AWT, part, Nn, Nn, ATT, (Nn / 32) / 8, (long long)Nn * ATT, nullptr);
        reduce_part<<<(Nn * ATT + 255) / 256, 256>>>(part, P1, Nn, ATT, 8, ab1[L], 1.f / SCALE_AW);

        attention_kernel<<<Nn / 4, 128>>>(P0, P1, aw2[L], ab2[L], rs0, rspart, a0, a1, dinv);

        // HW = h @ gw (SIMT, K=256), then HWT = HW^T
        gemm_nn_splitk<<<dim3(dout / 64, 32, 1), 256>>>(h, gw[L], part, Nn, dout, K, K);
        reduce_part<<<(Nn * dout + 255) / 256, 256>>>(part, HW, Nn, dout, 1, nullptr, 1.f);
        transpose_k<<<dim3(dout / 32, Nn / 32), dim3(32, 8)>>>(HW, HWT, Nn, dout, 1.f);

        // Build An (scaled by SCALE_AN) in place; stream final_A on last layer
        float* finalA = nullptr;
        if (L == 2 && out_size >= Nn * OUTD + Nn * Nn)
            finalA = (float*)d_out + (size_t)Nn * OUTD;
        build_An<<<16384, 256>>>(Ao, Am, a0, a1, dinv, finalA);

        // H2 = (An_scaled @ HW) / SCALE_AN + gb
        const int zsp = (dout == 256) ? 4 : 8;   // 256 CTAs
        gemm_f16<128, 0><<<dim3(dout / 128, 32, zsp), 256, SM128>>>(
            Am, HWT, part, Nn, Nn, dout, (Nn / 32) / zsp, (long long)Nn * dout, nullptr);
        reduce_part<<<(Nn * dout + 255) / 256, 256>>>(part, H2, Nn, dout, zsp, gb[L], 1.f / SCALE_AN);

        // BatchNorm + LeakyReLU -> H
        bn_stats<<<dout / 32, dim3(32, 8)>>>(H2, dout, mu, var);
        bn_apply<<<(Nn * dout + 255) / 256, 256>>>(H2, H, dout, mu, var, bng[L], bnb[L]);
        h = H;
    }

    // out = h @ lin_w + lin_b (K=128, SIMT)
    gemm_nn_splitk<<<dim3(1, 32, 1), 256>>>(h, lw, part, Nn, OUTD, 128, 128);
    reduce_part<<<(Nn * OUTD + 255) / 256, 256>>>(part, (float*)d_out, Nn, OUTD, 1, lb, 1.f);
}